// round 12
// baseline (speedup 1.0000x reference)
#include <cuda_runtime.h>
#include <cuda_fp16.h>
#include <cuda_bf16.h>
#include <math.h>
#include <stdint.h>

#define T_LEN 4096
#define B_SZ  16

// ---------------- scratch ----------------
__device__ float    g_raw  [16ll*1024*4096];
__device__ float    g_act32[16ll*512*4096];
__device__ float    g_z    [16ll*64*4096];
__device__ uint16_t g_hAh[16ll*4096*512], g_hAl[16ll*4096*512];
__device__ uint16_t g_hBh[16ll*4096*512], g_hBl[16ll*4096*512];
__device__ uint16_t g_xh [16ll*4096*128], g_xl [16ll*4096*128];
__device__ uint16_t g_yeh[16ll*4096*128];
__device__ uint16_t g_zvh[16ll*4096*64];
__device__ uint16_t g_wh [5ll*1024*640],  g_wl [5ll*1024*640];
__device__ float    g_wt [512*64];
__device__ float    g_cbt[64*512];
__device__ float    g_cbn[512];
__device__ float    g_spk[128*128];
__device__ int      g_idx[16*4096];

// ---------------- conversion helpers ----------------
__device__ __forceinline__ uint16_t f2bf(float v) {
    __nv_bfloat16 h = __float2bfloat16(v); return *(uint16_t*)&h;
}
__device__ __forceinline__ float bf2f(uint16_t u) {
    __nv_bfloat16 h = *(__nv_bfloat16*)&u; return __bfloat162float(h);
}
__device__ __forceinline__ uint16_t f2hf(float v) {
    __half h = __float2half(v); return *(uint16_t*)&h;
}

// ---------------- PTX helpers ----------------
__device__ __forceinline__ uint32_t s32(const void* p) {
    uint32_t a;
    asm("{ .reg .u64 t; cvta.to.shared.u64 t, %1; cvt.u32.u64 %0, t; }" : "=r"(a) : "l"(p));
    return a;
}
__device__ __forceinline__ void cpa16(uint32_t d, const void* s, bool v) {
    int sz = v ? 16 : 0;
    asm volatile("cp.async.cg.shared.global [%0], [%1], 16, %2;" :: "r"(d), "l"(s), "r"(sz) : "memory");
}
#define CP_COMMIT() asm volatile("cp.async.commit_group;" ::: "memory")
__device__ __forceinline__ void ldsm4(uint32_t* r, uint32_t a) {
    asm volatile("ldmatrix.sync.aligned.m8n8.x4.shared.b16 {%0,%1,%2,%3}, [%4];"
                 : "=r"(r[0]),"=r"(r[1]),"=r"(r[2]),"=r"(r[3]) : "r"(a));
}
__device__ __forceinline__ void ldsm2(uint32_t* r, uint32_t a) {
    asm volatile("ldmatrix.sync.aligned.m8n8.x2.shared.b16 {%0,%1}, [%2];"
                 : "=r"(r[0]),"=r"(r[1]) : "r"(a));
}
__device__ __forceinline__ void mma_bf16(float* d, const uint32_t* a, const uint32_t* b) {
    asm volatile("mma.sync.aligned.m16n8k16.row.col.f32.bf16.bf16.f32 "
                 "{%0,%1,%2,%3}, {%4,%5,%6,%7}, {%8,%9}, {%0,%1,%2,%3};"
                 : "+f"(d[0]), "+f"(d[1]), "+f"(d[2]), "+f"(d[3])
                 : "r"(a[0]), "r"(a[1]), "r"(a[2]), "r"(a[3]), "r"(b[0]), "r"(b[1]));
}
__device__ __forceinline__ void mma_f16(float* d, const uint32_t* a, const uint32_t* b) {
    asm volatile("mma.sync.aligned.m16n8k16.row.col.f32.f16.f16.f32 "
                 "{%0,%1,%2,%3}, {%4,%5,%6,%7}, {%8,%9}, {%0,%1,%2,%3};"
                 : "+f"(d[0]), "+f"(d[1]), "+f"(d[2]), "+f"(d[3])
                 : "r"(a[0]), "r"(a[1]), "r"(a[2]), "r"(a[3]), "r"(b[0]), "r"(b[1]));
}

// ---------------- mma.sync K=5 implicit conv GEMM ----------------
// Block tile 128co x 256t, 8 warps, warp tile 64co x 64t.
// MODE 0: bf16, A hi/lo + B hi/lo, 3 products (encoder)
// MODE 2: fp16, A single + B single, 1 product (decoder)
// grid (T/256, B, COUTP/128), block 256.
template<int CINP, int MODE>
__global__ void __launch_bounds__(256,1) gemm5_k(
    const uint16_t* __restrict__ in1h, const uint16_t* __restrict__ in1l, int C1,
    const uint16_t* __restrict__ in2h, const uint16_t* __restrict__ in2l,
    const uint16_t* __restrict__ wh,   const uint16_t* __restrict__ wl,
    const float* __restrict__ bias, int COUT, int COUTP,
    float* __restrict__ raw)
{
    constexpr int NCH  = CINP / 32;
    constexpr int ITER = NCH * 5;
    constexpr uint32_t B_HALF = 20800u;                       // 260 rows * 80B
    constexpr uint32_t B_BUF = (MODE == 0) ? 2u*B_HALF : B_HALF;
    constexpr uint32_t A_BUF = (MODE == 0) ? 20480u : 10240u; // 128 rows * 80B (x2 halves)
    extern __shared__ char smc[];
    const uint32_t sb = s32(smc);
    const uint32_t B_OFF0 = 0u, B_OFF1 = B_BUF;
    const uint32_t A_OFF0 = 2u * B_BUF, A_OFF1 = 2u * B_BUF + A_BUF;

    const int tid = threadIdx.x, lane = tid & 31, wid = tid >> 5;
    const int mw = wid & 1, nw = wid >> 1;
    const int t0 = blockIdx.x * 256, b = blockIdx.y, mo = blockIdx.z;

    float acc[4][8][4];
    #pragma unroll
    for (int i = 0; i < 4; i++)
        #pragma unroll
        for (int j = 0; j < 8; j++)
            #pragma unroll
            for (int q = 0; q < 4; q++) acc[i][j][q] = 0.f;

    const uint32_t aRow = (uint32_t)(((lane >> 3) & 1) * 8 + (lane & 7));
    const uint32_t aCol = (uint32_t)((lane >> 4) * 16);
    const uint32_t bRow = (uint32_t)(lane & 7);
    const uint32_t bCol = (uint32_t)((((lane & 15) >> 3)) * 16);

    auto issueB = [&](int ch, uint32_t boff) {
        int ci0 = ch * 32;
        const uint16_t *srch, *srcl; int Cs, off;
        if (ci0 < C1) { srch = in1h; srcl = in1l; Cs = C1;        off = ci0; }
        else          { srch = in2h; srcl = in2l; Cs = CINP - C1; off = ci0 - C1; }
        constexpr int BE = (MODE == 0) ? 2080 : 1040;  // 260 rows x 4 vec16 (x2 halves MODE0)
        for (int e = tid; e < BE; e += 256) {
            int half_ = (e >= 1040); int ee = half_ ? e - 1040 : e;
            int row = ee >> 2, v = ee & 3;
            int t = t0 - 2 + row;
            bool ok = (t >= 0) & (t < T_LEN);
            int tc = ok ? t : 0;
            uint32_t d = sb + boff + (uint32_t)half_ * B_HALF + (uint32_t)row * 80u + (uint32_t)v * 16u;
            const uint16_t* s = (half_ ? srcl : srch) + ((size_t)b * T_LEN + tc) * Cs + off + v * 8;
            cpa16(d, s, ok);
        }
    };
    auto issueA = [&](int it, uint32_t aoff) {
        int ch = it / 5, k = it % 5, ci0 = ch * 32;
        constexpr int AE = (MODE == 0) ? 1024 : 512;   // 128 rows x 4 vec16 (x2 halves MODE0)
        for (int e = tid; e < AE; e += 256) {
            int half_ = (e >= 512); int ee = e & 511;
            int row = ee >> 2, v = ee & 3;
            uint32_t d = sb + aoff + (uint32_t)half_ * 10240u + (uint32_t)row * 80u + (uint32_t)v * 16u;
            const uint16_t* s = (half_ ? wl : wh) + ((size_t)k * COUTP + mo * 128 + row) * CINP + ci0 + v * 8;
            cpa16(d, s, true);
        }
    };

    issueB(0, B_OFF0);
    issueA(0, A_OFF0);
    CP_COMMIT();

    for (int it = 0; it < ITER; it++) {
        int ch = it / 5, k = it % 5;
        uint32_t aoff = (it & 1) ? A_OFF1 : A_OFF0;
        uint32_t boff = (ch & 1) ? B_OFF1 : B_OFF0;
        if (it + 1 < ITER) {
            int ch1 = (it + 1) / 5;
            if (ch1 != ch) issueB(ch1, (ch1 & 1) ? B_OFF1 : B_OFF0);
            issueA(it + 1, ((it + 1) & 1) ? A_OFF1 : A_OFF0);
            CP_COMMIT();
            asm volatile("cp.async.wait_group 1;" ::: "memory");
        } else {
            asm volatile("cp.async.wait_group 0;" ::: "memory");
        }
        __syncthreads();

        uint32_t aH = sb + aoff + (uint32_t)(mw * 64) * 80u;
        uint32_t bH = sb + boff + (uint32_t)(nw * 64 + k) * 80u;
        #pragma unroll
        for (int ks = 0; ks < 2; ks++) {
            uint32_t ah[4][4], bh[8][2];
            uint32_t kOff = (uint32_t)ks * 32u;
            #pragma unroll
            for (int mt = 0; mt < 4; mt++) ldsm4(ah[mt], aH + (uint32_t)(mt * 16) * 80u + aRow * 80u + kOff + aCol);
            #pragma unroll
            for (int nt = 0; nt < 8; nt++) ldsm2(bh[nt], bH + (uint32_t)(nt * 8) * 80u + bRow * 80u + kOff + bCol);
            #pragma unroll
            for (int mt = 0; mt < 4; mt++)
                #pragma unroll
                for (int nt = 0; nt < 8; nt++) {
                    if constexpr (MODE == 0) mma_bf16(acc[mt][nt], ah[mt], bh[nt]);
                    else                     mma_f16 (acc[mt][nt], ah[mt], bh[nt]);
                }
            if constexpr (MODE == 0) {
                uint32_t bl[8][2], al[4][4];
                uint32_t bL = bH + B_HALF;
                uint32_t aL = aH + 10240u;
                #pragma unroll
                for (int nt = 0; nt < 8; nt++) ldsm2(bl[nt], bL + (uint32_t)(nt * 8) * 80u + bRow * 80u + kOff + bCol);
                #pragma unroll
                for (int mt = 0; mt < 4; mt++)
                    #pragma unroll
                    for (int nt = 0; nt < 8; nt++) mma_bf16(acc[mt][nt], ah[mt], bl[nt]);
                #pragma unroll
                for (int mt = 0; mt < 4; mt++) ldsm4(al[mt], aL + (uint32_t)(mt * 16) * 80u + aRow * 80u + kOff + aCol);
                #pragma unroll
                for (int mt = 0; mt < 4; mt++)
                    #pragma unroll
                    for (int nt = 0; nt < 8; nt++) mma_bf16(acc[mt][nt], al[mt], bh[nt]);
            }
        }
        __syncthreads();
    }

    // epilogue: bias + store raw [b][co][t]
    {
        int r = lane >> 2, c = (lane & 3) * 2;
        #pragma unroll
        for (int mt = 0; mt < 4; mt++) {
            int co0 = mo * 128 + mw * 64 + mt * 16 + r;
            int co1 = co0 + 8;
            float bv0 = (co0 < COUT) ? bias[co0] : 0.f;
            float bv1 = (co1 < COUT) ? bias[co1] : 0.f;
            #pragma unroll
            for (int nt = 0; nt < 8; nt++) {
                int t = t0 + nw * 64 + nt * 8 + c;
                float2 v0; v0.x = acc[mt][nt][0] + bv0; v0.y = acc[mt][nt][1] + bv0;
                float2 v1; v1.x = acc[mt][nt][2] + bv1; v1.y = acc[mt][nt][3] + bv1;
                *(float2*)(raw + ((size_t)b * COUTP + co0) * T_LEN + t) = v0;
                *(float2*)(raw + ((size_t)b * COUTP + co1) * T_LEN + t) = v1;
            }
        }
    }
}

// ---------------- LN + act + transpose + 16-bit output ----------------
// OUT: 0 = bf16 hi/lo pair, 1 = fp16 single, 2 = fp32 only
template<int CRAW,int GLU,int OUT,int EXF>
__global__ void __launch_bounds__(256) ln_k(const float* __restrict__ raw,
    const float* __restrict__ ga, const float* __restrict__ be,
    uint16_t* __restrict__ oh, uint16_t* __restrict__ ol, float* __restrict__ of)
{
    constexpr int COUT = GLU ? CRAW/2 : CRAW;
    __shared__ float sS[8][33], sQ[8][33], sM[32], sR[32];
    __shared__ uint16_t sTh[32*66], sTl[32*66];
    int b = blockIdx.y, t0 = blockIdx.x*32;
    int wg = threadIdx.x>>5, tt = threadIdx.x&31;
    const float* rb = raw + (size_t)b*CRAW*T_LEN + t0 + tt;
    float s=0.f, q=0.f;
    for (int c=wg; c<CRAW; c+=8){ float v=rb[(size_t)c*T_LEN]; s+=v; q+=v*v; }
    sS[wg][tt]=s; sQ[wg][tt]=q; __syncthreads();
    if (threadIdx.x<32){
        float S=0.f,Q=0.f;
        for(int g2=0;g2<8;g2++){S+=sS[g2][threadIdx.x];Q+=sQ[g2][threadIdx.x];}
        float m=S*(1.f/CRAW); float v=Q*(1.f/CRAW)-m*m;
        sM[threadIdx.x]=m; sR[threadIdx.x]=rsqrtf(v+1e-5f);
    }
    __syncthreads();
    float m=sM[tt], r=sR[tt];
    for (int c0=0;c0<COUT;c0+=64){
        #pragma unroll
        for (int i=0;i<8;i++){
            int c=c0+wg+8*i;
            float a=(rb[(size_t)c*T_LEN]-m)*r*ga[c]+be[c];
            if (GLU){
                float gt=(rb[(size_t)(c+COUT)*T_LEN]-m)*r*ga[c+COUT]+be[c+COUT];
                a=a*(1.f/(1.f+expf(-gt)));
            } else a = a>0.f? a : 0.2f*a;
            if (EXF) of[((size_t)b*COUT+c)*T_LEN + t0+tt] = a;
            if constexpr (OUT == 0) {
                uint16_t h = f2bf(a);
                sTh[tt*66 + wg+8*i] = h;
                sTl[tt*66 + wg+8*i] = f2bf(a - bf2f(h));
            } else if constexpr (OUT == 1) {
                sTh[tt*66 + wg+8*i] = f2hf(a);
            }
        }
        if constexpr (OUT != 2) {
            __syncthreads();
            {
                int row=threadIdx.x>>3, v=threadIdx.x&7;
                const uint32_t* ph=(const uint32_t*)sTh + row*33 + v*4;
                size_t go=((size_t)b*T_LEN + t0+row)*COUT + c0 + v*8;
                *(uint4*)(oh+go)=make_uint4(ph[0],ph[1],ph[2],ph[3]);
                if constexpr (OUT == 0) {
                    const uint32_t* pl=(const uint32_t*)sTl + row*33 + v*4;
                    *(uint4*)(ol+go)=make_uint4(pl[0],pl[1],pl[2],pl[3]);
                }
            }
            __syncthreads();
        }
    }
}

// ---------------- small helpers ----------------
__global__ void spknorm_k(const float* __restrict__ spk, float* __restrict__ o) {
    __shared__ float red[128];
    int r = blockIdx.x, t = threadIdx.x;
    float v = spk[r*128 + t];
    red[t] = v*v; __syncthreads();
    for (int s = 64; s > 0; s >>= 1) { if (t < s) red[t] += red[t+s]; __syncthreads(); }
    o[r*128 + t] = v * rsqrtf(red[0]);
}
__global__ void cbnorm_k(const float* __restrict__ cb, float* __restrict__ n) {
    int c = blockIdx.x*128 + threadIdx.x;
    if (c < 512) { float s=0.f; for (int d=0; d<64; d++){ float v=cb[c*64+d]; s+=v*v; } n[c]=s; }
}
__global__ void xprep_k(const float* __restrict__ x, uint16_t* __restrict__ oh, uint16_t* __restrict__ ol) {
    size_t e = (size_t)blockIdx.x*256 + threadIdx.x;
    int c = (int)(e & 127); size_t bt = e >> 7;
    float v = (c < 80) ? x[bt*80 + c] : 0.f;
    uint16_t h = f2bf(v);
    oh[e] = h; ol[e] = f2bf(v - bf2f(h));
}
__global__ void yeb_k(const int* __restrict__ y, const float* __restrict__ spk,
                      uint16_t* __restrict__ oh) {
    int b = blockIdx.y, t = blockIdx.x*8 + (threadIdx.x>>5), lid = threadIdx.x & 31;
    int yi = y[(size_t)b*T_LEN + t];
    size_t base = ((size_t)b*T_LEN + t) * 128;
    for (int c = lid; c < 128; c += 32)
        oh[base+c] = f2hf(spk[yi*128 + c]);
}
__global__ void zvqb_k(const int* __restrict__ idx, const float* __restrict__ cb,
                       uint16_t* __restrict__ oh) {
    int b = blockIdx.y, t = blockIdx.x*8 + (threadIdx.x>>5), lid = threadIdx.x & 31;
    int ii = idx[(size_t)b*T_LEN + t];
    size_t base = ((size_t)b*T_LEN + t) * 64;
    for (int c = lid; c < 64; c += 32)
        oh[base+c] = f2hf(cb[ii*64 + c]);
}
__global__ void out_k(const float* __restrict__ raw, float* __restrict__ out) {
    int b = blockIdx.y, tt = threadIdx.x & 31, g = threadIdx.x >> 5;
    int t = blockIdx.x*32 + tt;
    for (int f = g; f < 80; f += 8)
        out[((size_t)b*T_LEN + t)*80 + f] = raw[((size_t)b*128 + f)*T_LEN + t];
}
// mode 0: bf16 hi/lo (encoder); mode 1: fp16 single (decoder; dec handles ConvT flip)
__global__ void wprep_k(const float* __restrict__ w, uint16_t* __restrict__ wh, uint16_t* __restrict__ wl,
                        int CIN, int COUT, int CINP, int COUTP, int K, int dec, int mode) {
    long e = (long)blockIdx.x*256 + threadIdx.x;
    if (e >= (long)K*COUTP*CINP) return;
    int ci = (int)(e % CINP); long r0 = e / CINP; int co = (int)(r0 % COUTP); int k = (int)(r0 / COUTP);
    float v = 0.f;
    if (ci < CIN && co < COUT)
        v = dec ? w[((size_t)ci*COUT + co)*K + (K-1-k)] : w[((size_t)co*CIN + ci)*K + k];
    if (mode == 0) {
        uint16_t h = f2bf(v);
        wh[e] = h; wl[e] = f2bf(v - bf2f(h));
    } else {
        wh[e] = f2hf(v);
    }
}
__global__ void wtrans_k(const float* __restrict__ w, float* __restrict__ wt, int CIN, int COUT) {
    int e = blockIdx.x*256 + threadIdx.x;
    if (e >= CIN*COUT) return;
    int co = e % COUT, ci = e / COUT;
    wt[e] = w[(size_t)co*CIN + ci];
}

// ---------------- fp32 1x1 conv (mlp / VQ argmin) ----------------
template<int CIN,int COUT,int G_CO,int TPT,int EPI>
__global__ __launch_bounds__(256,2) void mm_k(
    const float* __restrict__ in, const float* __restrict__ wt,
    const float* __restrict__ bias, float* __restrict__ out, int* __restrict__ oidx)
{
    constexpr int CIB=16, G_T=256/G_CO, TT=G_T*TPT, CPT=COUT/G_CO;
    constexpr int WE=CIB*COUT, IE=CIB*TT, NCB=CIN/CIB, RS=G_CO+1;
    extern __shared__ float smf[];
    float* sW=smf; float* sI=sW+WE; float* sRa=sI+IE; int* sRi=(int*)(sRa+TT*RS);
    const int tid=threadIdx.x, cg=tid%G_CO, tg=tid/G_CO;
    const int b=blockIdx.y, t0=blockIdx.x*TT;
    float acc[CPT][TPT];
    #pragma unroll
    for (int i=0;i<CPT;i++)
        #pragma unroll
        for (int t=0;t<TPT;t++) acc[i][t]=0.f;
    for (int cb=0; cb<NCB; cb++) {
        __syncthreads();
        const float* ws = wt + (size_t)cb*WE;
        for (int e=tid; e<WE; e+=256) sW[e]=ws[e];
        for (int e=tid; e<IE; e+=256) {
            int ci=e/TT, j=e%TT;
            sI[e] = in[((size_t)b*CIN + cb*CIB + ci)*T_LEN + t0 + j];
        }
        __syncthreads();
        #pragma unroll 1
        for (int ci=0; ci<CIB; ci++) {
            float rin[TPT];
            #pragma unroll
            for (int j=0;j<TPT;j++) rin[j]=sI[ci*TT + tg*TPT + j];
            #pragma unroll
            for (int i=0;i<CPT;i++) {
                float wv = sW[ci*COUT + cg + G_CO*i];
                #pragma unroll
                for (int t=0;t<TPT;t++) acc[i][t]=fmaf(wv, rin[t], acc[i][t]);
            }
        }
    }
    if constexpr (EPI == 1) {
        float bv[CPT];
        #pragma unroll
        for (int i=0;i<CPT;i++) bv[i]=bias[cg + G_CO*i];
        #pragma unroll
        for (int t=0;t<TPT;t++) {
            float best=3.4e38f; int bi=0;
            #pragma unroll
            for (int i=0;i<CPT;i++) {
                float v=bv[i]-2.f*acc[i][t]; int ii=cg+G_CO*i;
                if (v<best || (v==best && ii<bi)) { best=v; bi=ii; }
            }
            int tl=tg*TPT+t;
            sRa[tl*RS+cg]=best; sRi[tl*RS+cg]=bi;
        }
        __syncthreads();
        if (tid < TT) {
            float best=3.4e38f; int bi=0;
            for (int g=0; g<G_CO; g++) {
                float v=sRa[tid*RS+g]; int ii=sRi[tid*RS+g];
                if (v<best || (v==best && ii<bi)) { best=v; bi=ii; }
            }
            oidx[(size_t)b*T_LEN + t0 + tid] = bi;
        }
    } else {
        #pragma unroll
        for (int i=0;i<CPT;i++) {
            int co=cg+G_CO*i;
            float bv=bias[co];
            #pragma unroll
            for (int t=0;t<TPT;t++)
                out[((size_t)b*COUT+co)*T_LEN + t0 + tg*TPT + t] = acc[i][t]+bv;
        }
    }
}

// ---------------- launch ----------------
#define GEMM5(CINP_, MODE_, i1h,i1l,C1_, i2h,i2l, biasp, COUT_, COUTP_) do { \
    constexpr int SMB_ = ((MODE_) == 0) ? (2*(2*20800) + 2*20480) : (2*20800 + 2*10240); \
    auto kf = &gemm5_k<CINP_, MODE_>; \
    cudaFuncSetAttribute(kf, cudaFuncAttributeMaxDynamicSharedMemorySize, SMB_); \
    kf<<<dim3(16, B_SZ, (COUTP_)/128), 256, SMB_>>>(i1h,i1l,C1_, i2h,i2l, wh,wl, biasp, COUT_, COUTP_, raw); \
} while (0)

extern "C" void kernel_launch(void* const* d_in, const int* in_sizes, int n_in,
                              void* d_out, int out_size) {
    (void)in_sizes; (void)n_in; (void)out_size;
    const float* x       = (const float*)d_in[0];
    const int*   y       = (const int*)  d_in[1];
    const float* enc_w1  = (const float*)d_in[2];
    const float* enc_b1  = (const float*)d_in[3];
    const float* enc_g1  = (const float*)d_in[4];
    const float* enc_bt1 = (const float*)d_in[5];
    const float* enc_w2  = (const float*)d_in[6];
    const float* enc_b2  = (const float*)d_in[7];
    const float* enc_g2  = (const float*)d_in[8];
    const float* enc_bt2 = (const float*)d_in[9];
    const float* enc_w3  = (const float*)d_in[10];
    const float* enc_b3  = (const float*)d_in[11];
    const float* enc_g3  = (const float*)d_in[12];
    const float* enc_bt3 = (const float*)d_in[13];
    const float* mlp_w   = (const float*)d_in[14];
    const float* mlp_b   = (const float*)d_in[15];
    const float* codebook= (const float*)d_in[16];
    const float* spk_emb = (const float*)d_in[17];
    const float* dec_w1  = (const float*)d_in[18];
    const float* dec_b1  = (const float*)d_in[19];
    const float* dec_g1  = (const float*)d_in[20];
    const float* dec_bt1 = (const float*)d_in[21];
    const float* dec_w2  = (const float*)d_in[22];
    const float* dec_b2  = (const float*)d_in[23];
    const float* dec_g2  = (const float*)d_in[24];
    const float* dec_bt2 = (const float*)d_in[25];
    const float* dec_w3  = (const float*)d_in[26];
    const float* dec_b3  = (const float*)d_in[27];
    float* outp = (float*)d_out;

    float *raw,*act32,*z,*wt,*cbt,*cbn,*spk; int* idx;
    uint16_t *hAh,*hAl,*hBh,*hBl,*xh,*xl,*yeh,*zvh,*wh,*wl;
    cudaGetSymbolAddress((void**)&raw,  g_raw);
    cudaGetSymbolAddress((void**)&act32,g_act32);
    cudaGetSymbolAddress((void**)&z,    g_z);
    cudaGetSymbolAddress((void**)&hAh,  g_hAh);  cudaGetSymbolAddress((void**)&hAl, g_hAl);
    cudaGetSymbolAddress((void**)&hBh,  g_hBh);  cudaGetSymbolAddress((void**)&hBl, g_hBl);
    cudaGetSymbolAddress((void**)&xh,   g_xh);   cudaGetSymbolAddress((void**)&xl,  g_xl);
    cudaGetSymbolAddress((void**)&yeh,  g_yeh);
    cudaGetSymbolAddress((void**)&zvh,  g_zvh);
    cudaGetSymbolAddress((void**)&wh,   g_wh);   cudaGetSymbolAddress((void**)&wl,  g_wl);
    cudaGetSymbolAddress((void**)&wt,   g_wt);
    cudaGetSymbolAddress((void**)&cbt,  g_cbt);
    cudaGetSymbolAddress((void**)&cbn,  g_cbn);
    cudaGetSymbolAddress((void**)&spk,  g_spk);
    cudaGetSymbolAddress((void**)&idx,  g_idx);

    // input prep
    xprep_k<<<(B_SZ*T_LEN*128)/256, 256>>>(x, xh, xl);
    spknorm_k<<<128, 128>>>(spk_emb, spk);
    yeb_k<<<dim3(T_LEN/8, B_SZ), 256>>>(y, spk, yeh);

    // ===== encoder: bf16 3-product (MODE 0) =====
    wprep_k<<<(5*512*128+255)/256, 256>>>(enc_w1, wh, wl, 80, 512, 128, 512, 5, 0, 0);
    GEMM5(128, 0, xh, xl, 128, (const uint16_t*)nullptr, (const uint16_t*)nullptr, enc_b1, 512, 512);
    ln_k<512,0,0,0><<<dim3(128, B_SZ), 256>>>(raw, enc_g1, enc_bt1, hAh, hAl, nullptr);
    wprep_k<<<(5*512*512+255)/256, 256>>>(enc_w2, wh, wl, 512, 512, 512, 512, 5, 0, 0);
    GEMM5(512, 0, hAh, hAl, 512, (const uint16_t*)nullptr, (const uint16_t*)nullptr, enc_b2, 512, 512);
    ln_k<512,0,0,0><<<dim3(128, B_SZ), 256>>>(raw, enc_g2, enc_bt2, hBh, hBl, nullptr);
    wprep_k<<<(5*512*512+255)/256, 256>>>(enc_w3, wh, wl, 512, 512, 512, 512, 5, 0, 0);
    GEMM5(512, 0, hBh, hBl, 512, (const uint16_t*)nullptr, (const uint16_t*)nullptr, enc_b3, 512, 512);
    ln_k<512,0,2,1><<<dim3(128, B_SZ), 256>>>(raw, enc_g3, enc_bt3, nullptr, nullptr, act32);

    // ===== mlp + VQ (exact fp32) =====
    wtrans_k<<<(512*64+255)/256, 256>>>(mlp_w, wt, 512, 64);
    mm_k<512,64,32,8,0><<<dim3(T_LEN/64, B_SZ), 256, (16*64+16*64+64*33*2)*4>>>(act32, wt, mlp_b, z, nullptr);
    wtrans_k<<<(64*512+255)/256, 256>>>(codebook, cbt, 64, 512);
    cbnorm_k<<<4, 128>>>(codebook, cbn);
    {
        constexpr int SB = (16*512 + 16*32 + 32*65*2)*4;
        auto kf = &mm_k<64,512,64,8,1>;
        cudaFuncSetAttribute(kf, cudaFuncAttributeMaxDynamicSharedMemorySize, SB);
        kf<<<dim3(T_LEN/32, B_SZ), 256, SB>>>(z, cbt, cbn, nullptr, idx);
    }
    zvqb_k<<<dim3(T_LEN/8, B_SZ), 256>>>(idx, codebook, zvh);

    // ===== decoder: fp16 1-product (MODE 2) =====
    wprep_k<<<(5*1024*192+255)/256, 256>>>(dec_w1, wh, wl, 192, 1024, 192, 1024, 5, 1, 1);
    GEMM5(192, 2, zvh, (const uint16_t*)nullptr, 64, yeh, (const uint16_t*)nullptr, dec_b1, 1024, 1024);
    ln_k<1024,1,1,0><<<dim3(128, B_SZ), 256>>>(raw, dec_g1, dec_bt1, hAh, nullptr, nullptr);
    wprep_k<<<(5*1024*640+255)/256, 256>>>(dec_w2, wh, wl, 640, 1024, 640, 1024, 5, 1, 1);
    GEMM5(640, 2, hAh, (const uint16_t*)nullptr, 512, yeh, (const uint16_t*)nullptr, dec_b2, 1024, 1024);
    ln_k<1024,1,1,0><<<dim3(128, B_SZ), 256>>>(raw, dec_g2, dec_bt2, hBh, nullptr, nullptr);
    wprep_k<<<(5*128*640+255)/256, 256>>>(dec_w3, wh, wl, 640, 80, 640, 128, 5, 1, 1);
    GEMM5(640, 2, hBh, (const uint16_t*)nullptr, 512, yeh, (const uint16_t*)nullptr, dec_b3, 80, 128);
    out_k<<<dim3(T_LEN/32, B_SZ), 256>>>(raw, outp);
}

// round 13
// speedup vs baseline: 1.0578x; 1.0578x over previous
#include <cuda_runtime.h>
#include <cuda_fp16.h>
#include <cuda_bf16.h>
#include <math.h>
#include <stdint.h>

#define T_LEN 4096
#define B_SZ  16

// ---------------- scratch ----------------
__device__ float    g_raw  [16ll*1024*4096];
__device__ float    g_act32[16ll*512*4096];
__device__ float    g_z    [16ll*64*4096];
__device__ uint16_t g_hAh[16ll*4096*512], g_hAl[16ll*4096*512];
__device__ uint16_t g_hBh[16ll*4096*512], g_hBl[16ll*4096*512];
__device__ uint16_t g_xh [16ll*4096*128], g_xl [16ll*4096*128];
__device__ uint16_t g_yeh[16ll*4096*128];
__device__ uint16_t g_zvh[16ll*4096*64];
__device__ uint16_t g_wh [5ll*1024*640],  g_wl [5ll*1024*640];
__device__ float    g_wt [512*64];
__device__ float    g_cbt[64*512];
__device__ float    g_cbn[512];
__device__ float    g_spk[128*128];
__device__ int      g_idx[16*4096];

// ---------------- conversion helpers ----------------
__device__ __forceinline__ uint16_t f2bf(float v) {
    __nv_bfloat16 h = __float2bfloat16(v); return *(uint16_t*)&h;
}
__device__ __forceinline__ float bf2f(uint16_t u) {
    __nv_bfloat16 h = *(__nv_bfloat16*)&u; return __bfloat162float(h);
}
__device__ __forceinline__ uint16_t f2hf(float v) {
    __half h = __float2half(v); return *(uint16_t*)&h;
}

// ---------------- PTX helpers ----------------
__device__ __forceinline__ uint32_t s32(const void* p) {
    uint32_t a;
    asm("{ .reg .u64 t; cvta.to.shared.u64 t, %1; cvt.u32.u64 %0, t; }" : "=r"(a) : "l"(p));
    return a;
}
__device__ __forceinline__ void cpa16(uint32_t d, const void* s, bool v) {
    int sz = v ? 16 : 0;
    asm volatile("cp.async.cg.shared.global [%0], [%1], 16, %2;" :: "r"(d), "l"(s), "r"(sz) : "memory");
}
#define CP_COMMIT() asm volatile("cp.async.commit_group;" ::: "memory")
__device__ __forceinline__ void ldsm4(uint32_t* r, uint32_t a) {
    asm volatile("ldmatrix.sync.aligned.m8n8.x4.shared.b16 {%0,%1,%2,%3}, [%4];"
                 : "=r"(r[0]),"=r"(r[1]),"=r"(r[2]),"=r"(r[3]) : "r"(a));
}
__device__ __forceinline__ void mma_bf16(float* d, const uint32_t* a, const uint32_t* b) {
    asm volatile("mma.sync.aligned.m16n8k16.row.col.f32.bf16.bf16.f32 "
                 "{%0,%1,%2,%3}, {%4,%5,%6,%7}, {%8,%9}, {%0,%1,%2,%3};"
                 : "+f"(d[0]), "+f"(d[1]), "+f"(d[2]), "+f"(d[3])
                 : "r"(a[0]), "r"(a[1]), "r"(a[2]), "r"(a[3]), "r"(b[0]), "r"(b[1]));
}
__device__ __forceinline__ void mma_f16(float* d, const uint32_t* a, const uint32_t* b) {
    asm volatile("mma.sync.aligned.m16n8k16.row.col.f32.f16.f16.f32 "
                 "{%0,%1,%2,%3}, {%4,%5,%6,%7}, {%8,%9}, {%0,%1,%2,%3};"
                 : "+f"(d[0]), "+f"(d[1]), "+f"(d[2]), "+f"(d[3])
                 : "r"(a[0]), "r"(a[1]), "r"(a[2]), "r"(a[3]), "r"(b[0]), "r"(b[1]));
}

// ---------------- mma.sync K=5 implicit conv GEMM ----------------
// Block tile 128co x 128t, 8 warps, warp tile 64co x 32t (R10 proven config).
// MODE 0: bf16, A hi/lo + B hi/lo, 3 products (encoder)
// MODE 2: fp16, A single + B single, 1 product (decoder)
// TRANS 1: dec3 path — write output [b][t][80] directly.
// grid (T/128, B, COUTP/128), block 256.
template<int CINP, int MODE, int TRANS>
__global__ void __launch_bounds__(256,2) gemm5_k(
    const uint16_t* __restrict__ in1h, const uint16_t* __restrict__ in1l, int C1,
    const uint16_t* __restrict__ in2h, const uint16_t* __restrict__ in2l,
    const uint16_t* __restrict__ wh,   const uint16_t* __restrict__ wl,
    const float* __restrict__ bias, int COUT, int COUTP,
    float* __restrict__ raw)
{
    constexpr int NCH  = CINP / 32;
    constexpr int ITER = NCH * 5;
    constexpr uint32_t B_BUF = (MODE == 0) ? 21120u : 10560u;
    constexpr uint32_t A_BUF = (MODE == 0) ? 20480u : 10240u;
    extern __shared__ char smc[];
    const uint32_t sb = s32(smc);
    const uint32_t B_OFF0 = 0u, B_OFF1 = B_BUF;
    const uint32_t A_OFF0 = 2u * B_BUF, A_OFF1 = 2u * B_BUF + A_BUF;

    const int tid = threadIdx.x, lane = tid & 31, wid = tid >> 5;
    const int mw = wid & 1, nw = wid >> 1;
    const int t0 = blockIdx.x * 128, b = blockIdx.y, mo = blockIdx.z;

    float acc[4][4][4];
    #pragma unroll
    for (int i = 0; i < 4; i++)
        #pragma unroll
        for (int j = 0; j < 4; j++)
            #pragma unroll
            for (int q = 0; q < 4; q++) acc[i][j][q] = 0.f;

    // A ldmatrix lane map (row=bit3, col=bit4)
    const uint32_t aRow = (uint32_t)(((lane >> 3) & 1) * 8 + (lane & 7));
    const uint32_t aCol = (uint32_t)((lane >> 4) * 16);
    // B ldmatrix-x4 lane map (row=bit4, col=bit3): one x4 covers TWO adjacent n-tiles
    const uint32_t bRow2 = (uint32_t)(((lane >> 4) & 1) * 8 + (lane & 7));
    const uint32_t bCol2 = (uint32_t)(((lane >> 3) & 1) * 16);

    auto issueB = [&](int ch, uint32_t boff) {
        int ci0 = ch * 32;
        const uint16_t *srch, *srcl; int Cs, off;
        if (ci0 < C1) { srch = in1h; srcl = in1l; Cs = C1;        off = ci0; }
        else          { srch = in2h; srcl = in2l; Cs = CINP - C1; off = ci0 - C1; }
        constexpr int BE = (MODE == 0) ? 1056 : 528;
        for (int e = tid; e < BE; e += 256) {
            int half_ = (e >= 528); int ee = half_ ? e - 528 : e;
            int row = ee >> 2, v = ee & 3;
            int t = t0 - 2 + row;
            bool ok = (t >= 0) & (t < T_LEN);
            int tc = ok ? t : 0;
            uint32_t d = sb + boff + (uint32_t)half_ * 10560u + (uint32_t)row * 80u + (uint32_t)v * 16u;
            const uint16_t* s = (half_ ? srcl : srch) + ((size_t)b * T_LEN + tc) * Cs + off + v * 8;
            cpa16(d, s, ok);
        }
    };
    auto issueA = [&](int it, uint32_t aoff) {
        int ch = it / 5, k = it % 5, ci0 = ch * 32;
        constexpr int AE = (MODE == 0) ? 1024 : 512;
        for (int e = tid; e < AE; e += 256) {
            int half_ = (e >= 512); int ee = e & 511;
            int row = ee >> 2, v = ee & 3;
            uint32_t d = sb + aoff + (uint32_t)half_ * 10240u + (uint32_t)row * 80u + (uint32_t)v * 16u;
            const uint16_t* s = (half_ ? wl : wh) + ((size_t)k * COUTP + mo * 128 + row) * CINP + ci0 + v * 8;
            cpa16(d, s, true);
        }
    };

    issueB(0, B_OFF0);
    issueA(0, A_OFF0);
    CP_COMMIT();

    for (int it = 0; it < ITER; it++) {
        int ch = it / 5, k = it % 5;
        uint32_t aoff = (it & 1) ? A_OFF1 : A_OFF0;
        uint32_t boff = (ch & 1) ? B_OFF1 : B_OFF0;
        // single-sync pipeline: drain pending group (this iter's data), barrier,
        // then issue next iter's loads (post-barrier => no WAR hazard), then mma.
        asm volatile("cp.async.wait_group 0;" ::: "memory");
        __syncthreads();
        if (it + 1 < ITER) {
            int ch1 = (it + 1) / 5;
            if (ch1 != ch) issueB(ch1, (ch1 & 1) ? B_OFF1 : B_OFF0);
            issueA(it + 1, ((it + 1) & 1) ? A_OFF1 : A_OFF0);
            CP_COMMIT();
        }

        uint32_t aH = sb + aoff + (uint32_t)(mw * 64) * 80u;
        uint32_t bB = sb + boff + (uint32_t)(nw * 32 + k) * 80u;
        #pragma unroll
        for (int ks = 0; ks < 2; ks++) {
            uint32_t ah[4][4], bqh[2][4];
            uint32_t kOff = (uint32_t)ks * 32u;
            #pragma unroll
            for (int mt = 0; mt < 4; mt++) ldsm4(ah[mt], aH + (uint32_t)(mt * 16) * 80u + aRow * 80u + kOff + aCol);
            #pragma unroll
            for (int np = 0; np < 2; np++) ldsm4(bqh[np], bB + ((uint32_t)(np * 16) + bRow2) * 80u + kOff + bCol2);
            #pragma unroll
            for (int mt = 0; mt < 4; mt++)
                #pragma unroll
                for (int nt = 0; nt < 4; nt++) {
                    const uint32_t* bp = &bqh[nt >> 1][2 * (nt & 1)];
                    if constexpr (MODE == 0) mma_bf16(acc[mt][nt], ah[mt], bp);
                    else                     mma_f16 (acc[mt][nt], ah[mt], bp);
                }
            if constexpr (MODE == 0) {
                uint32_t bql[2][4], al[4][4];
                uint32_t bL = bB + 10560u;
                uint32_t aL = aH + 10240u;
                #pragma unroll
                for (int np = 0; np < 2; np++) ldsm4(bql[np], bL + ((uint32_t)(np * 16) + bRow2) * 80u + kOff + bCol2);
                #pragma unroll
                for (int mt = 0; mt < 4; mt++)
                    #pragma unroll
                    for (int nt = 0; nt < 4; nt++) mma_bf16(acc[mt][nt], ah[mt], &bql[nt >> 1][2 * (nt & 1)]);
                #pragma unroll
                for (int mt = 0; mt < 4; mt++) ldsm4(al[mt], aL + (uint32_t)(mt * 16) * 80u + aRow * 80u + kOff + aCol);
                #pragma unroll
                for (int mt = 0; mt < 4; mt++)
                    #pragma unroll
                    for (int nt = 0; nt < 4; nt++) mma_bf16(acc[mt][nt], al[mt], &bqh[nt >> 1][2 * (nt & 1)]);
            }
        }
    }

    // epilogue
    {
        int r = lane >> 2, c = (lane & 3) * 2;
        #pragma unroll
        for (int mt = 0; mt < 4; mt++) {
            int co0 = mo * 128 + mw * 64 + mt * 16 + r;
            int co1 = co0 + 8;
            float bv0 = (co0 < COUT) ? bias[co0] : 0.f;
            float bv1 = (co1 < COUT) ? bias[co1] : 0.f;
            #pragma unroll
            for (int nt = 0; nt < 4; nt++) {
                int t = t0 + nw * 32 + nt * 8 + c;
                if constexpr (TRANS) {
                    // direct [b][t][80] output (dec3)
                    if (co0 < COUT) {
                        raw[((size_t)b * T_LEN + t)     * COUT + co0] = acc[mt][nt][0] + bv0;
                        raw[((size_t)b * T_LEN + t + 1) * COUT + co0] = acc[mt][nt][1] + bv0;
                    }
                    if (co1 < COUT) {
                        raw[((size_t)b * T_LEN + t)     * COUT + co1] = acc[mt][nt][2] + bv1;
                        raw[((size_t)b * T_LEN + t + 1) * COUT + co1] = acc[mt][nt][3] + bv1;
                    }
                } else {
                    float2 v0; v0.x = acc[mt][nt][0] + bv0; v0.y = acc[mt][nt][1] + bv0;
                    float2 v1; v1.x = acc[mt][nt][2] + bv1; v1.y = acc[mt][nt][3] + bv1;
                    *(float2*)(raw + ((size_t)b * COUTP + co0) * T_LEN + t) = v0;
                    *(float2*)(raw + ((size_t)b * COUTP + co1) * T_LEN + t) = v1;
                }
            }
        }
    }
}

// ---------------- LN + act + transpose + 16-bit output ----------------
// OUT: 0 = bf16 hi/lo pair, 1 = fp16 single, 2 = fp32 only
template<int CRAW,int GLU,int OUT,int EXF>
__global__ void __launch_bounds__(256) ln_k(const float* __restrict__ raw,
    const float* __restrict__ ga, const float* __restrict__ be,
    uint16_t* __restrict__ oh, uint16_t* __restrict__ ol, float* __restrict__ of)
{
    constexpr int COUT = GLU ? CRAW/2 : CRAW;
    __shared__ float sS[8][33], sQ[8][33], sM[32], sR[32];
    __shared__ uint16_t sTh[32*66], sTl[32*66];
    int b = blockIdx.y, t0 = blockIdx.x*32;
    int wg = threadIdx.x>>5, tt = threadIdx.x&31;
    const float* rb = raw + (size_t)b*CRAW*T_LEN + t0 + tt;
    float s=0.f, q=0.f;
    for (int c=wg; c<CRAW; c+=8){ float v=rb[(size_t)c*T_LEN]; s+=v; q+=v*v; }
    sS[wg][tt]=s; sQ[wg][tt]=q; __syncthreads();
    if (threadIdx.x<32){
        float S=0.f,Q=0.f;
        for(int g2=0;g2<8;g2++){S+=sS[g2][threadIdx.x];Q+=sQ[g2][threadIdx.x];}
        float m=S*(1.f/CRAW); float v=Q*(1.f/CRAW)-m*m;
        sM[threadIdx.x]=m; sR[threadIdx.x]=rsqrtf(v+1e-5f);
    }
    __syncthreads();
    float m=sM[tt], r=sR[tt];
    for (int c0=0;c0<COUT;c0+=64){
        #pragma unroll
        for (int i=0;i<8;i++){
            int c=c0+wg+8*i;
            float a=(rb[(size_t)c*T_LEN]-m)*r*ga[c]+be[c];
            if (GLU){
                float gt=(rb[(size_t)(c+COUT)*T_LEN]-m)*r*ga[c+COUT]+be[c+COUT];
                a=a*(1.f/(1.f+expf(-gt)));
            } else a = a>0.f? a : 0.2f*a;
            if (EXF) of[((size_t)b*COUT+c)*T_LEN + t0+tt] = a;
            if constexpr (OUT == 0) {
                uint16_t h = f2bf(a);
                sTh[tt*66 + wg+8*i] = h;
                sTl[tt*66 + wg+8*i] = f2bf(a - bf2f(h));
            } else if constexpr (OUT == 1) {
                sTh[tt*66 + wg+8*i] = f2hf(a);
            }
        }
        if constexpr (OUT != 2) {
            __syncthreads();
            {
                int row=threadIdx.x>>3, v=threadIdx.x&7;
                const uint32_t* ph=(const uint32_t*)sTh + row*33 + v*4;
                size_t go=((size_t)b*T_LEN + t0+row)*COUT + c0 + v*8;
                *(uint4*)(oh+go)=make_uint4(ph[0],ph[1],ph[2],ph[3]);
                if constexpr (OUT == 0) {
                    const uint32_t* pl=(const uint32_t*)sTl + row*33 + v*4;
                    *(uint4*)(ol+go)=make_uint4(pl[0],pl[1],pl[2],pl[3]);
                }
            }
            __syncthreads();
        }
    }
}

// ---------------- small helpers ----------------
__global__ void spknorm_k(const float* __restrict__ spk, float* __restrict__ o) {
    __shared__ float red[128];
    int r = blockIdx.x, t = threadIdx.x;
    float v = spk[r*128 + t];
    red[t] = v*v; __syncthreads();
    for (int s = 64; s > 0; s >>= 1) { if (t < s) red[t] += red[t+s]; __syncthreads(); }
    o[r*128 + t] = v * rsqrtf(red[0]);
}
__global__ void cbnorm_k(const float* __restrict__ cb, float* __restrict__ n) {
    int c = blockIdx.x*128 + threadIdx.x;
    if (c < 512) { float s=0.f; for (int d=0; d<64; d++){ float v=cb[c*64+d]; s+=v*v; } n[c]=s; }
}
__global__ void xprep_k(const float* __restrict__ x, uint16_t* __restrict__ oh, uint16_t* __restrict__ ol) {
    size_t e = (size_t)blockIdx.x*256 + threadIdx.x;
    int c = (int)(e & 127); size_t bt = e >> 7;
    float v = (c < 80) ? x[bt*80 + c] : 0.f;
    uint16_t h = f2bf(v);
    oh[e] = h; ol[e] = f2bf(v - bf2f(h));
}
__global__ void yeb_k(const int* __restrict__ y, const float* __restrict__ spk,
                      uint16_t* __restrict__ oh) {
    int b = blockIdx.y, t = blockIdx.x*8 + (threadIdx.x>>5), lid = threadIdx.x & 31;
    int yi = y[(size_t)b*T_LEN + t];
    size_t base = ((size_t)b*T_LEN + t) * 128;
    for (int c = lid; c < 128; c += 32)
        oh[base+c] = f2hf(spk[yi*128 + c]);
}
__global__ void zvqb_k(const int* __restrict__ idx, const float* __restrict__ cb,
                       uint16_t* __restrict__ oh) {
    int b = blockIdx.y, t = blockIdx.x*8 + (threadIdx.x>>5), lid = threadIdx.x & 31;
    int ii = idx[(size_t)b*T_LEN + t];
    size_t base = ((size_t)b*T_LEN + t) * 64;
    for (int c = lid; c < 64; c += 32)
        oh[base+c] = f2hf(cb[ii*64 + c]);
}
// mode 0: bf16 hi/lo (encoder); mode 1: fp16 single (decoder; dec handles ConvT flip)
__global__ void wprep_k(const float* __restrict__ w, uint16_t* __restrict__ wh, uint16_t* __restrict__ wl,
                        int CIN, int COUT, int CINP, int COUTP, int K, int dec, int mode) {
    long e = (long)blockIdx.x*256 + threadIdx.x;
    if (e >= (long)K*COUTP*CINP) return;
    int ci = (int)(e % CINP); long r0 = e / CINP; int co = (int)(r0 % COUTP); int k = (int)(r0 / COUTP);
    float v = 0.f;
    if (ci < CIN && co < COUT)
        v = dec ? w[((size_t)ci*COUT + co)*K + (K-1-k)] : w[((size_t)co*CIN + ci)*K + k];
    if (mode == 0) {
        uint16_t h = f2bf(v);
        wh[e] = h; wl[e] = f2bf(v - bf2f(h));
    } else {
        wh[e] = f2hf(v);
    }
}
__global__ void wtrans_k(const float* __restrict__ w, float* __restrict__ wt, int CIN, int COUT) {
    int e = blockIdx.x*256 + threadIdx.x;
    if (e >= CIN*COUT) return;
    int co = e % COUT, ci = e / COUT;
    wt[e] = w[(size_t)co*CIN + ci];
}

// ---------------- fp32 1x1 conv (mlp / VQ argmin) ----------------
template<int CIN,int COUT,int G_CO,int TPT,int EPI>
__global__ __launch_bounds__(256,2) void mm_k(
    const float* __restrict__ in, const float* __restrict__ wt,
    const float* __restrict__ bias, float* __restrict__ out, int* __restrict__ oidx)
{
    constexpr int CIB=16, G_T=256/G_CO, TT=G_T*TPT, CPT=COUT/G_CO;
    constexpr int WE=CIB*COUT, IE=CIB*TT, NCB=CIN/CIB, RS=G_CO+1;
    extern __shared__ float smf[];
    float* sW=smf; float* sI=sW+WE; float* sRa=sI+IE; int* sRi=(int*)(sRa+TT*RS);
    const int tid=threadIdx.x, cg=tid%G_CO, tg=tid/G_CO;
    const int b=blockIdx.y, t0=blockIdx.x*TT;
    float acc[CPT][TPT];
    #pragma unroll
    for (int i=0;i<CPT;i++)
        #pragma unroll
        for (int t=0;t<TPT;t++) acc[i][t]=0.f;
    for (int cb=0; cb<NCB; cb++) {
        __syncthreads();
        const float* ws = wt + (size_t)cb*WE;
        for (int e=tid; e<WE; e+=256) sW[e]=ws[e];
        for (int e=tid; e<IE; e+=256) {
            int ci=e/TT, j=e%TT;
            sI[e] = in[((size_t)b*CIN + cb*CIB + ci)*T_LEN + t0 + j];
        }
        __syncthreads();
        #pragma unroll 1
        for (int ci=0; ci<CIB; ci++) {
            float rin[TPT];
            #pragma unroll
            for (int j=0;j<TPT;j++) rin[j]=sI[ci*TT + tg*TPT + j];
            #pragma unroll
            for (int i=0;i<CPT;i++) {
                float wv = sW[ci*COUT + cg + G_CO*i];
                #pragma unroll
                for (int t=0;t<TPT;t++) acc[i][t]=fmaf(wv, rin[t], acc[i][t]);
            }
        }
    }
    if constexpr (EPI == 1) {
        float bv[CPT];
        #pragma unroll
        for (int i=0;i<CPT;i++) bv[i]=bias[cg + G_CO*i];
        #pragma unroll
        for (int t=0;t<TPT;t++) {
            float best=3.4e38f; int bi=0;
            #pragma unroll
            for (int i=0;i<CPT;i++) {
                float v=bv[i]-2.f*acc[i][t]; int ii=cg+G_CO*i;
                if (v<best || (v==best && ii<bi)) { best=v; bi=ii; }
            }
            int tl=tg*TPT+t;
            sRa[tl*RS+cg]=best; sRi[tl*RS+cg]=bi;
        }
        __syncthreads();
        if (tid < TT) {
            float best=3.4e38f; int bi=0;
            for (int g=0; g<G_CO; g++) {
                float v=sRa[tid*RS+g]; int ii=sRi[tid*RS+g];
                if (v<best || (v==best && ii<bi)) { best=v; bi=ii; }
            }
            oidx[(size_t)b*T_LEN + t0 + tid] = bi;
        }
    } else {
        #pragma unroll
        for (int i=0;i<CPT;i++) {
            int co=cg+G_CO*i;
            float bv=bias[co];
            #pragma unroll
            for (int t=0;t<TPT;t++)
                out[((size_t)b*COUT+co)*T_LEN + t0 + tg*TPT + t] = acc[i][t]+bv;
        }
    }
}

// ---------------- launch ----------------
#define GEMM5(CINP_, MODE_, TR_, i1h,i1l,C1_, i2h,i2l, biasp, COUT_, COUTP_, outp_) do { \
    constexpr int SMB_ = ((MODE_) == 0) ? (2*21120 + 2*20480) : (2*10560 + 2*10240); \
    auto kf = &gemm5_k<CINP_, MODE_, TR_>; \
    cudaFuncSetAttribute(kf, cudaFuncAttributeMaxDynamicSharedMemorySize, SMB_); \
    kf<<<dim3(32, B_SZ, (COUTP_)/128), 256, SMB_>>>(i1h,i1l,C1_, i2h,i2l, wh,wl, biasp, COUT_, COUTP_, outp_); \
} while (0)

extern "C" void kernel_launch(void* const* d_in, const int* in_sizes, int n_in,
                              void* d_out, int out_size) {
    (void)in_sizes; (void)n_in; (void)out_size;
    const float* x       = (const float*)d_in[0];
    const int*   y       = (const int*)  d_in[1];
    const float* enc_w1  = (const float*)d_in[2];
    const float* enc_b1  = (const float*)d_in[3];
    const float* enc_g1  = (const float*)d_in[4];
    const float* enc_bt1 = (const float*)d_in[5];
    const float* enc_w2  = (const float*)d_in[6];
    const float* enc_b2  = (const float*)d_in[7];
    const float* enc_g2  = (const float*)d_in[8];
    const float* enc_bt2 = (const float*)d_in[9];
    const float* enc_w3  = (const float*)d_in[10];
    const float* enc_b3  = (const float*)d_in[11];
    const float* enc_g3  = (const float*)d_in[12];
    const float* enc_bt3 = (const float*)d_in[13];
    const float* mlp_w   = (const float*)d_in[14];
    const float* mlp_b   = (const float*)d_in[15];
    const float* codebook= (const float*)d_in[16];
    const float* spk_emb = (const float*)d_in[17];
    const float* dec_w1  = (const float*)d_in[18];
    const float* dec_b1  = (const float*)d_in[19];
    const float* dec_g1  = (const float*)d_in[20];
    const float* dec_bt1 = (const float*)d_in[21];
    const float* dec_w2  = (const float*)d_in[22];
    const float* dec_b2  = (const float*)d_in[23];
    const float* dec_g2  = (const float*)d_in[24];
    const float* dec_bt2 = (const float*)d_in[25];
    const float* dec_w3  = (const float*)d_in[26];
    const float* dec_b3  = (const float*)d_in[27];
    float* outp = (float*)d_out;

    float *raw,*act32,*z,*wt,*cbt,*cbn,*spk; int* idx;
    uint16_t *hAh,*hAl,*hBh,*hBl,*xh,*xl,*yeh,*zvh,*wh,*wl;
    cudaGetSymbolAddress((void**)&raw,  g_raw);
    cudaGetSymbolAddress((void**)&act32,g_act32);
    cudaGetSymbolAddress((void**)&z,    g_z);
    cudaGetSymbolAddress((void**)&hAh,  g_hAh);  cudaGetSymbolAddress((void**)&hAl, g_hAl);
    cudaGetSymbolAddress((void**)&hBh,  g_hBh);  cudaGetSymbolAddress((void**)&hBl, g_hBl);
    cudaGetSymbolAddress((void**)&xh,   g_xh);   cudaGetSymbolAddress((void**)&xl,  g_xl);
    cudaGetSymbolAddress((void**)&yeh,  g_yeh);
    cudaGetSymbolAddress((void**)&zvh,  g_zvh);
    cudaGetSymbolAddress((void**)&wh,   g_wh);   cudaGetSymbolAddress((void**)&wl,  g_wl);
    cudaGetSymbolAddress((void**)&wt,   g_wt);
    cudaGetSymbolAddress((void**)&cbt,  g_cbt);
    cudaGetSymbolAddress((void**)&cbn,  g_cbn);
    cudaGetSymbolAddress((void**)&spk,  g_spk);
    cudaGetSymbolAddress((void**)&idx,  g_idx);

    // input prep
    xprep_k<<<(B_SZ*T_LEN*128)/256, 256>>>(x, xh, xl);
    spknorm_k<<<128, 128>>>(spk_emb, spk);
    yeb_k<<<dim3(T_LEN/8, B_SZ), 256>>>(y, spk, yeh);

    // ===== encoder: bf16 3-product (MODE 0) =====
    wprep_k<<<(5*512*128+255)/256, 256>>>(enc_w1, wh, wl, 80, 512, 128, 512, 5, 0, 0);
    GEMM5(128, 0, 0, xh, xl, 128, (const uint16_t*)nullptr, (const uint16_t*)nullptr, enc_b1, 512, 512, raw);
    ln_k<512,0,0,0><<<dim3(128, B_SZ), 256>>>(raw, enc_g1, enc_bt1, hAh, hAl, nullptr);
    wprep_k<<<(5*512*512+255)/256, 256>>>(enc_w2, wh, wl, 512, 512, 512, 512, 5, 0, 0);
    GEMM5(512, 0, 0, hAh, hAl, 512, (const uint16_t*)nullptr, (const uint16_t*)nullptr, enc_b2, 512, 512, raw);
    ln_k<512,0,0,0><<<dim3(128, B_SZ), 256>>>(raw, enc_g2, enc_bt2, hBh, hBl, nullptr);
    wprep_k<<<(5*512*512+255)/256, 256>>>(enc_w3, wh, wl, 512, 512, 512, 512, 5, 0, 0);
    GEMM5(512, 0, 0, hBh, hBl, 512, (const uint16_t*)nullptr, (const uint16_t*)nullptr, enc_b3, 512, 512, raw);
    ln_k<512,0,2,1><<<dim3(128, B_SZ), 256>>>(raw, enc_g3, enc_bt3, nullptr, nullptr, act32);

    // ===== mlp + VQ (exact fp32) =====
    wtrans_k<<<(512*64+255)/256, 256>>>(mlp_w, wt, 512, 64);
    mm_k<512,64,32,8,0><<<dim3(T_LEN/64, B_SZ), 256, (16*64+16*64+64*33*2)*4>>>(act32, wt, mlp_b, z, nullptr);
    wtrans_k<<<(64*512+255)/256, 256>>>(codebook, cbt, 64, 512);
    cbnorm_k<<<4, 128>>>(codebook, cbn);
    {
        constexpr int SB = (16*512 + 16*32 + 32*65*2)*4;
        auto kf = &mm_k<64,512,64,8,1>;
        cudaFuncSetAttribute(kf, cudaFuncAttributeMaxDynamicSharedMemorySize, SB);
        kf<<<dim3(T_LEN/32, B_SZ), 256, SB>>>(z, cbt, cbn, nullptr, idx);
    }
    zvqb_k<<<dim3(T_LEN/8, B_SZ), 256>>>(idx, codebook, zvh);

    // ===== decoder: fp16 1-product (MODE 2) =====
    wprep_k<<<(5*1024*192+255)/256, 256>>>(dec_w1, wh, wl, 192, 1024, 192, 1024, 5, 1, 1);
    GEMM5(192, 2, 0, zvh, (const uint16_t*)nullptr, 64, yeh, (const uint16_t*)nullptr, dec_b1, 1024, 1024, raw);
    ln_k<1024,1,1,0><<<dim3(128, B_SZ), 256>>>(raw, dec_g1, dec_bt1, hAh, nullptr, nullptr);
    wprep_k<<<(5*1024*640+255)/256, 256>>>(dec_w2, wh, wl, 640, 1024, 640, 1024, 5, 1, 1);
    GEMM5(640, 2, 0, hAh, (const uint16_t*)nullptr, 512, yeh, (const uint16_t*)nullptr, dec_b2, 1024, 1024, raw);
    ln_k<1024,1,1,0><<<dim3(128, B_SZ), 256>>>(raw, dec_g2, dec_bt2, hBh, nullptr, nullptr);
    wprep_k<<<(5*128*640+255)/256, 256>>>(dec_w3, wh, wl, 640, 80, 640, 128, 5, 1, 1);
    // dec3: direct transposed write into d_out (COUT=80)
    GEMM5(640, 2, 1, hBh, (const uint16_t*)nullptr, 512, yeh, (const uint16_t*)nullptr, dec_b3, 80, 128, outp);
}

// round 14
// speedup vs baseline: 1.1294x; 1.0677x over previous
#include <cuda_runtime.h>
#include <cuda_fp16.h>
#include <cuda_bf16.h>
#include <math.h>
#include <stdint.h>

#define T_LEN 4096
#define B_SZ  16

// ---------------- scratch ----------------
__device__ float    g_raw  [16ll*1024*4096];
__device__ uint16_t g_hAh[16ll*4096*512], g_hAl[16ll*4096*512];
__device__ uint16_t g_hBh[16ll*4096*512], g_hBl[16ll*4096*512];
__device__ uint16_t g_xh [16ll*4096*128], g_xl [16ll*4096*128];
__device__ uint16_t g_yeh[16ll*4096*128];
__device__ uint16_t g_zvh[16ll*4096*64];
__device__ uint16_t g_wh [5ll*1024*640],  g_wl [5ll*1024*640];
__device__ float    g_cbn[512];
__device__ float    g_spk[128*128];
__device__ int      g_idx[16*4096];

// ---------------- conversion helpers ----------------
__device__ __forceinline__ uint16_t f2bf(float v) {
    __nv_bfloat16 h = __float2bfloat16(v); return *(uint16_t*)&h;
}
__device__ __forceinline__ float bf2f(uint16_t u) {
    __nv_bfloat16 h = *(__nv_bfloat16*)&u; return __bfloat162float(h);
}
__device__ __forceinline__ uint16_t f2hf(float v) {
    __half h = __float2half(v); return *(uint16_t*)&h;
}

// ---------------- PTX helpers ----------------
__device__ __forceinline__ uint32_t s32(const void* p) {
    uint32_t a;
    asm("{ .reg .u64 t; cvta.to.shared.u64 t, %1; cvt.u32.u64 %0, t; }" : "=r"(a) : "l"(p));
    return a;
}
__device__ __forceinline__ void cpa16(uint32_t d, const void* s, bool v) {
    int sz = v ? 16 : 0;
    asm volatile("cp.async.cg.shared.global [%0], [%1], 16, %2;" :: "r"(d), "l"(s), "r"(sz) : "memory");
}
#define CP_COMMIT() asm volatile("cp.async.commit_group;" ::: "memory")
__device__ __forceinline__ void ldsm4(uint32_t* r, uint32_t a) {
    asm volatile("ldmatrix.sync.aligned.m8n8.x4.shared.b16 {%0,%1,%2,%3}, [%4];"
                 : "=r"(r[0]),"=r"(r[1]),"=r"(r[2]),"=r"(r[3]) : "r"(a));
}
__device__ __forceinline__ void mma_bf16(float* d, const uint32_t* a, const uint32_t* b) {
    asm volatile("mma.sync.aligned.m16n8k16.row.col.f32.bf16.bf16.f32 "
                 "{%0,%1,%2,%3}, {%4,%5,%6,%7}, {%8,%9}, {%0,%1,%2,%3};"
                 : "+f"(d[0]), "+f"(d[1]), "+f"(d[2]), "+f"(d[3])
                 : "r"(a[0]), "r"(a[1]), "r"(a[2]), "r"(a[3]), "r"(b[0]), "r"(b[1]));
}
__device__ __forceinline__ void mma_f16(float* d, const uint32_t* a, const uint32_t* b) {
    asm volatile("mma.sync.aligned.m16n8k16.row.col.f32.f16.f16.f32 "
                 "{%0,%1,%2,%3}, {%4,%5,%6,%7}, {%8,%9}, {%0,%1,%2,%3};"
                 : "+f"(d[0]), "+f"(d[1]), "+f"(d[2]), "+f"(d[3])
                 : "r"(a[0]), "r"(a[1]), "r"(a[2]), "r"(a[3]), "r"(b[0]), "r"(b[1]));
}

// ---------------- mma.sync implicit conv GEMM (K taps templated) ----------------
// Block tile 128co x 128t, 8 warps, warp tile 64co x 32t.
// MODE 0: bf16, A hi/lo + B hi/lo, 3 products (encoder / mlp / VQ)
// MODE 2: fp16, A single + B single, 1 product (decoder)
// EPI 0: raw [b][co][t] = acc + bias
// EPI 1: direct out [b][t][COUT] = acc + bias (dec3)
// EPI 2: raw [b][co][t] = bias - 2*acc (VQ scores)
template<int CINP, int MODE, int KS, int EPI>
__global__ void __launch_bounds__(256,2) gemm5_k(
    const uint16_t* __restrict__ in1h, const uint16_t* __restrict__ in1l, int C1,
    const uint16_t* __restrict__ in2h, const uint16_t* __restrict__ in2l,
    const uint16_t* __restrict__ wh,   const uint16_t* __restrict__ wl,
    const float* __restrict__ bias, int COUT, int COUTP,
    float* __restrict__ raw)
{
    constexpr int NCH  = CINP / 32;
    constexpr int ITER = NCH * KS;
    constexpr int PAD  = (KS - 1) / 2;
    constexpr int IROWS = 128 + KS - 1;
    constexpr uint32_t B_BUF = (MODE == 0) ? 21120u : 10560u;
    constexpr uint32_t A_BUF = (MODE == 0) ? 20480u : 10240u;
    extern __shared__ char smc[];
    const uint32_t sb = s32(smc);
    const uint32_t B_OFF0 = 0u, B_OFF1 = B_BUF;
    const uint32_t A_OFF0 = 2u * B_BUF, A_OFF1 = 2u * B_BUF + A_BUF;

    const int tid = threadIdx.x, lane = tid & 31, wid = tid >> 5;
    const int mw = wid & 1, nw = wid >> 1;
    const int t0 = blockIdx.x * 128, b = blockIdx.y, mo = blockIdx.z;

    float acc[4][4][4];
    #pragma unroll
    for (int i = 0; i < 4; i++)
        #pragma unroll
        for (int j = 0; j < 4; j++)
            #pragma unroll
            for (int q = 0; q < 4; q++) acc[i][j][q] = 0.f;

    const uint32_t aRow = (uint32_t)(((lane >> 3) & 1) * 8 + (lane & 7));
    const uint32_t aCol = (uint32_t)((lane >> 4) * 16);
    const uint32_t bRow2 = (uint32_t)(((lane >> 4) & 1) * 8 + (lane & 7));
    const uint32_t bCol2 = (uint32_t)(((lane >> 3) & 1) * 16);

    auto issueB = [&](int ch, uint32_t boff) {
        int ci0 = ch * 32;
        const uint16_t *srch, *srcl; int Cs, off;
        if (ci0 < C1) { srch = in1h; srcl = in1l; Cs = C1;        off = ci0; }
        else          { srch = in2h; srcl = in2l; Cs = CINP - C1; off = ci0 - C1; }
        constexpr int HALF_E = IROWS * 4;
        constexpr int BE = (MODE == 0) ? 2 * HALF_E : HALF_E;
        for (int e = tid; e < BE; e += 256) {
            int half_ = (e >= HALF_E); int ee = half_ ? e - HALF_E : e;
            int row = ee >> 2, v = ee & 3;
            int t = t0 - PAD + row;
            bool ok = (t >= 0) & (t < T_LEN);
            int tc = ok ? t : 0;
            uint32_t d = sb + boff + (uint32_t)half_ * 10560u + (uint32_t)row * 80u + (uint32_t)v * 16u;
            const uint16_t* s = (half_ ? srcl : srch) + ((size_t)b * T_LEN + tc) * Cs + off + v * 8;
            cpa16(d, s, ok);
        }
    };
    auto issueA = [&](int it, uint32_t aoff) {
        int ch = it / KS, k = it % KS, ci0 = ch * 32;
        constexpr int AE = (MODE == 0) ? 1024 : 512;
        for (int e = tid; e < AE; e += 256) {
            int half_ = (e >= 512); int ee = e & 511;
            int row = ee >> 2, v = ee & 3;
            uint32_t d = sb + aoff + (uint32_t)half_ * 10240u + (uint32_t)row * 80u + (uint32_t)v * 16u;
            const uint16_t* s = (half_ ? wl : wh) + ((size_t)k * COUTP + mo * 128 + row) * CINP + ci0 + v * 8;
            cpa16(d, s, true);
        }
    };

    issueB(0, B_OFF0);
    issueA(0, A_OFF0);
    CP_COMMIT();

    for (int it = 0; it < ITER; it++) {
        int ch = it / KS, k = it % KS;
        uint32_t aoff = (it & 1) ? A_OFF1 : A_OFF0;
        uint32_t boff = (ch & 1) ? B_OFF1 : B_OFF0;
        asm volatile("cp.async.wait_group 0;" ::: "memory");
        __syncthreads();
        if (it + 1 < ITER) {
            int ch1 = (it + 1) / KS;
            if (ch1 != ch) issueB(ch1, (ch1 & 1) ? B_OFF1 : B_OFF0);
            issueA(it + 1, ((it + 1) & 1) ? A_OFF1 : A_OFF0);
            CP_COMMIT();
        }

        uint32_t aH = sb + aoff + (uint32_t)(mw * 64) * 80u;
        uint32_t bB = sb + boff + (uint32_t)(nw * 32 + k) * 80u;
        #pragma unroll
        for (int ks = 0; ks < 2; ks++) {
            uint32_t ah[4][4], bqh[2][4];
            uint32_t kOff = (uint32_t)ks * 32u;
            #pragma unroll
            for (int mt = 0; mt < 4; mt++) ldsm4(ah[mt], aH + (uint32_t)(mt * 16) * 80u + aRow * 80u + kOff + aCol);
            #pragma unroll
            for (int np = 0; np < 2; np++) ldsm4(bqh[np], bB + ((uint32_t)(np * 16) + bRow2) * 80u + kOff + bCol2);
            #pragma unroll
            for (int mt = 0; mt < 4; mt++)
                #pragma unroll
                for (int nt = 0; nt < 4; nt++) {
                    const uint32_t* bp = &bqh[nt >> 1][2 * (nt & 1)];
                    if constexpr (MODE == 0) mma_bf16(acc[mt][nt], ah[mt], bp);
                    else                     mma_f16 (acc[mt][nt], ah[mt], bp);
                }
            if constexpr (MODE == 0) {
                uint32_t bql[2][4], al[4][4];
                uint32_t bL = bB + 10560u;
                uint32_t aL = aH + 10240u;
                #pragma unroll
                for (int np = 0; np < 2; np++) ldsm4(bql[np], bL + ((uint32_t)(np * 16) + bRow2) * 80u + kOff + bCol2);
                #pragma unroll
                for (int mt = 0; mt < 4; mt++)
                    #pragma unroll
                    for (int nt = 0; nt < 4; nt++) mma_bf16(acc[mt][nt], ah[mt], &bql[nt >> 1][2 * (nt & 1)]);
                #pragma unroll
                for (int mt = 0; mt < 4; mt++) ldsm4(al[mt], aL + (uint32_t)(mt * 16) * 80u + aRow * 80u + kOff + aCol);
                #pragma unroll
                for (int mt = 0; mt < 4; mt++)
                    #pragma unroll
                    for (int nt = 0; nt < 4; nt++) mma_bf16(acc[mt][nt], al[mt], &bqh[nt >> 1][2 * (nt & 1)]);
            }
        }
    }

    // epilogue
    {
        int r = lane >> 2, c = (lane & 3) * 2;
        #pragma unroll
        for (int mt = 0; mt < 4; mt++) {
            int co0 = mo * 128 + mw * 64 + mt * 16 + r;
            int co1 = co0 + 8;
            float bv0 = (co0 < COUT) ? bias[co0] : 0.f;
            float bv1 = (co1 < COUT) ? bias[co1] : 0.f;
            #pragma unroll
            for (int nt = 0; nt < 4; nt++) {
                int t = t0 + nw * 32 + nt * 8 + c;
                if constexpr (EPI == 1) {
                    if (co0 < COUT) {
                        raw[((size_t)b * T_LEN + t)     * COUT + co0] = acc[mt][nt][0] + bv0;
                        raw[((size_t)b * T_LEN + t + 1) * COUT + co0] = acc[mt][nt][1] + bv0;
                    }
                    if (co1 < COUT) {
                        raw[((size_t)b * T_LEN + t)     * COUT + co1] = acc[mt][nt][2] + bv1;
                        raw[((size_t)b * T_LEN + t + 1) * COUT + co1] = acc[mt][nt][3] + bv1;
                    }
                } else if constexpr (EPI == 2) {
                    float2 v0; v0.x = bv0 - 2.f*acc[mt][nt][0]; v0.y = bv0 - 2.f*acc[mt][nt][1];
                    float2 v1; v1.x = bv1 - 2.f*acc[mt][nt][2]; v1.y = bv1 - 2.f*acc[mt][nt][3];
                    *(float2*)(raw + ((size_t)b * COUTP + co0) * T_LEN + t) = v0;
                    *(float2*)(raw + ((size_t)b * COUTP + co1) * T_LEN + t) = v1;
                } else {
                    float2 v0; v0.x = acc[mt][nt][0] + bv0; v0.y = acc[mt][nt][1] + bv0;
                    float2 v1; v1.x = acc[mt][nt][2] + bv1; v1.y = acc[mt][nt][3] + bv1;
                    *(float2*)(raw + ((size_t)b * COUTP + co0) * T_LEN + t) = v0;
                    *(float2*)(raw + ((size_t)b * COUTP + co1) * T_LEN + t) = v1;
                }
            }
        }
    }
}

// ---------------- LN + act + transpose + 16-bit output ----------------
// OUT: 0 = bf16 hi/lo pair, 1 = fp16 single
template<int CRAW,int GLU,int OUT>
__global__ void __launch_bounds__(256) ln_k(const float* __restrict__ raw,
    const float* __restrict__ ga, const float* __restrict__ be,
    uint16_t* __restrict__ oh, uint16_t* __restrict__ ol)
{
    constexpr int COUT = GLU ? CRAW/2 : CRAW;
    __shared__ float sS[8][33], sQ[8][33], sM[32], sR[32];
    __shared__ uint16_t sTh[32*66], sTl[32*66];
    int b = blockIdx.y, t0 = blockIdx.x*32;
    int wg = threadIdx.x>>5, tt = threadIdx.x&31;
    const float* rb = raw + (size_t)b*CRAW*T_LEN + t0 + tt;
    float s=0.f, q=0.f;
    for (int c=wg; c<CRAW; c+=8){ float v=rb[(size_t)c*T_LEN]; s+=v; q+=v*v; }
    sS[wg][tt]=s; sQ[wg][tt]=q; __syncthreads();
    if (threadIdx.x<32){
        float S=0.f,Q=0.f;
        for(int g2=0;g2<8;g2++){S+=sS[g2][threadIdx.x];Q+=sQ[g2][threadIdx.x];}
        float m=S*(1.f/CRAW); float v=Q*(1.f/CRAW)-m*m;
        sM[threadIdx.x]=m; sR[threadIdx.x]=rsqrtf(v+1e-5f);
    }
    __syncthreads();
    float m=sM[tt], r=sR[tt];
    for (int c0=0;c0<COUT;c0+=64){
        #pragma unroll
        for (int i=0;i<8;i++){
            int c=c0+wg+8*i;
            float a=(rb[(size_t)c*T_LEN]-m)*r*ga[c]+be[c];
            if (GLU){
                float gt=(rb[(size_t)(c+COUT)*T_LEN]-m)*r*ga[c+COUT]+be[c+COUT];
                a=a*(1.f/(1.f+expf(-gt)));
            } else a = a>0.f? a : 0.2f*a;
            if constexpr (OUT == 0) {
                uint16_t h = f2bf(a);
                sTh[tt*66 + wg+8*i] = h;
                sTl[tt*66 + wg+8*i] = f2bf(a - bf2f(h));
            } else {
                sTh[tt*66 + wg+8*i] = f2hf(a);
            }
        }
        __syncthreads();
        {
            int row=threadIdx.x>>3, v=threadIdx.x&7;
            const uint32_t* ph=(const uint32_t*)sTh + row*33 + v*4;
            size_t go=((size_t)b*T_LEN + t0+row)*COUT + c0 + v*8;
            *(uint4*)(oh+go)=make_uint4(ph[0],ph[1],ph[2],ph[3]);
            if constexpr (OUT == 0) {
                const uint32_t* pl=(const uint32_t*)sTl + row*33 + v*4;
                *(uint4*)(ol+go)=make_uint4(pl[0],pl[1],pl[2],pl[3]);
            }
        }
        __syncthreads();
    }
}

// ---------------- z split: raw [b][128][t] (64 valid) -> bf16 hi/lo [b][t][64] ----------------
__global__ void __launch_bounds__(256) zsplit_k(const float* __restrict__ raw,
    uint16_t* __restrict__ oh, uint16_t* __restrict__ ol)
{
    __shared__ uint16_t sTh[32*66], sTl[32*66];
    int b = blockIdx.y, t0 = blockIdx.x*32;
    int wg = threadIdx.x>>5, tt = threadIdx.x&31;
    const float* rb = raw + (size_t)b*128*T_LEN + t0 + tt;
    #pragma unroll
    for (int i=0;i<8;i++){
        int c=wg+8*i;
        float a=rb[(size_t)c*T_LEN];
        uint16_t h = f2bf(a);
        sTh[tt*66 + c] = h;
        sTl[tt*66 + c] = f2bf(a - bf2f(h));
    }
    __syncthreads();
    {
        int row=threadIdx.x>>3, v=threadIdx.x&7;
        const uint32_t* ph=(const uint32_t*)sTh + row*33 + v*4;
        const uint32_t* pl=(const uint32_t*)sTl + row*33 + v*4;
        size_t go=((size_t)b*T_LEN + t0+row)*64 + v*8;
        *(uint4*)(oh+go)=make_uint4(ph[0],ph[1],ph[2],ph[3]);
        *(uint4*)(ol+go)=make_uint4(pl[0],pl[1],pl[2],pl[3]);
    }
}

// ---------------- VQ argmin over scores raw [b][512][t] ----------------
__global__ void __launch_bounds__(256) argmin_k(const float* __restrict__ sc, int* __restrict__ idx)
{
    int b = blockIdx.y, t = blockIdx.x*256 + threadIdx.x;
    const float* p = sc + (size_t)b*512*T_LEN + t;
    float best = 3.4e38f; int bi = 0;
    for (int c = 0; c < 512; c++) {
        float v = p[(size_t)c*T_LEN];
        if (v < best) { best = v; bi = c; }
    }
    idx[(size_t)b*T_LEN + t] = bi;
}

// ---------------- small helpers ----------------
__global__ void spknorm_k(const float* __restrict__ spk, float* __restrict__ o) {
    __shared__ float red[128];
    int r = blockIdx.x, t = threadIdx.x;
    float v = spk[r*128 + t];
    red[t] = v*v; __syncthreads();
    for (int s = 64; s > 0; s >>= 1) { if (t < s) red[t] += red[t+s]; __syncthreads(); }
    o[r*128 + t] = v * rsqrtf(red[0]);
}
__global__ void cbnorm_k(const float* __restrict__ cb, float* __restrict__ n) {
    int c = blockIdx.x*128 + threadIdx.x;
    if (c < 512) { float s=0.f; for (int d=0; d<64; d++){ float v=cb[c*64+d]; s+=v*v; } n[c]=s; }
}
__global__ void xprep_k(const float* __restrict__ x, uint16_t* __restrict__ oh, uint16_t* __restrict__ ol) {
    long e = (long)blockIdx.x*256 + threadIdx.x;
    if (e >= (long)B_SZ*T_LEN*96) return;
    int c = (int)(e % 96); long bt = e / 96;
    float v = (c < 80) ? x[bt*80 + c] : 0.f;
    uint16_t h = f2bf(v);
    oh[e] = h; ol[e] = f2bf(v - bf2f(h));
}
__global__ void yeb_k(const int* __restrict__ y, const float* __restrict__ spk,
                      uint16_t* __restrict__ oh) {
    int b = blockIdx.y, t = blockIdx.x*8 + (threadIdx.x>>5), lid = threadIdx.x & 31;
    int yi = y[(size_t)b*T_LEN + t];
    size_t base = ((size_t)b*T_LEN + t) * 128;
    for (int c = lid; c < 128; c += 32)
        oh[base+c] = f2hf(spk[yi*128 + c]);
}
__global__ void zvqb_k(const int* __restrict__ idx, const float* __restrict__ cb,
                       uint16_t* __restrict__ oh) {
    int b = blockIdx.y, t = blockIdx.x*8 + (threadIdx.x>>5), lid = threadIdx.x & 31;
    int ii = idx[(size_t)b*T_LEN + t];
    size_t base = ((size_t)b*T_LEN + t) * 64;
    for (int c = lid; c < 64; c += 32)
        oh[base+c] = f2hf(cb[ii*64 + c]);
}
// mode 0: bf16 hi/lo; mode 1: fp16 single. dec=1 does ConvT flip/transpose.
__global__ void wprep_k(const float* __restrict__ w, uint16_t* __restrict__ wh, uint16_t* __restrict__ wl,
                        int CIN, int COUT, int CINP, int COUTP, int K, int dec, int mode) {
    long e = (long)blockIdx.x*256 + threadIdx.x;
    if (e >= (long)K*COUTP*CINP) return;
    int ci = (int)(e % CINP); long r0 = e / CINP; int co = (int)(r0 % COUTP); int k = (int)(r0 / COUTP);
    float v = 0.f;
    if (ci < CIN && co < COUT)
        v = dec ? w[((size_t)ci*COUT + co)*K + (K-1-k)] : w[((size_t)co*CIN + ci)*K + k];
    if (mode == 0) {
        uint16_t h = f2bf(v);
        wh[e] = h; wl[e] = f2bf(v - bf2f(h));
    } else {
        wh[e] = f2hf(v);
    }
}

// ---------------- launch ----------------
#define GEMM5(CINP_, MODE_, KS_, EPI_, i1h,i1l,C1_, i2h,i2l, biasp, COUT_, COUTP_, outp_) do { \
    constexpr int SMB_ = ((MODE_) == 0) ? (2*21120 + 2*20480) : (2*10560 + 2*10240); \
    auto kf = &gemm5_k<CINP_, MODE_, KS_, EPI_>; \
    cudaFuncSetAttribute(kf, cudaFuncAttributeMaxDynamicSharedMemorySize, SMB_); \
    kf<<<dim3(32, B_SZ, (COUTP_)/128), 256, SMB_>>>(i1h,i1l,C1_, i2h,i2l, wh,wl, biasp, COUT_, COUTP_, outp_); \
} while (0)

extern "C" void kernel_launch(void* const* d_in, const int* in_sizes, int n_in,
                              void* d_out, int out_size) {
    (void)in_sizes; (void)n_in; (void)out_size;
    const float* x       = (const float*)d_in[0];
    const int*   y       = (const int*)  d_in[1];
    const float* enc_w1  = (const float*)d_in[2];
    const float* enc_b1  = (const float*)d_in[3];
    const float* enc_g1  = (const float*)d_in[4];
    const float* enc_bt1 = (const float*)d_in[5];
    const float* enc_w2  = (const float*)d_in[6];
    const float* enc_b2  = (const float*)d_in[7];
    const float* enc_g2  = (const float*)d_in[8];
    const float* enc_bt2 = (const float*)d_in[9];
    const float* enc_w3  = (const float*)d_in[10];
    const float* enc_b3  = (const float*)d_in[11];
    const float* enc_g3  = (const float*)d_in[12];
    const float* enc_bt3 = (const float*)d_in[13];
    const float* mlp_w   = (const float*)d_in[14];
    const float* mlp_b   = (const float*)d_in[15];
    const float* codebook= (const float*)d_in[16];
    const float* spk_emb = (const float*)d_in[17];
    const float* dec_w1  = (const float*)d_in[18];
    const float* dec_b1  = (const float*)d_in[19];
    const float* dec_g1  = (const float*)d_in[20];
    const float* dec_bt1 = (const float*)d_in[21];
    const float* dec_w2  = (const float*)d_in[22];
    const float* dec_b2  = (const float*)d_in[23];
    const float* dec_g2  = (const float*)d_in[24];
    const float* dec_bt2 = (const float*)d_in[25];
    const float* dec_w3  = (const float*)d_in[26];
    const float* dec_b3  = (const float*)d_in[27];
    float* outp = (float*)d_out;

    float *raw,*cbn,*spk; int* idx;
    uint16_t *hAh,*hAl,*hBh,*hBl,*xh,*xl,*yeh,*zvh,*wh,*wl;
    cudaGetSymbolAddress((void**)&raw,  g_raw);
    cudaGetSymbolAddress((void**)&hAh,  g_hAh);  cudaGetSymbolAddress((void**)&hAl, g_hAl);
    cudaGetSymbolAddress((void**)&hBh,  g_hBh);  cudaGetSymbolAddress((void**)&hBl, g_hBl);
    cudaGetSymbolAddress((void**)&xh,   g_xh);   cudaGetSymbolAddress((void**)&xl,  g_xl);
    cudaGetSymbolAddress((void**)&yeh,  g_yeh);
    cudaGetSymbolAddress((void**)&zvh,  g_zvh);
    cudaGetSymbolAddress((void**)&wh,   g_wh);   cudaGetSymbolAddress((void**)&wl,  g_wl);
    cudaGetSymbolAddress((void**)&cbn,  g_cbn);
    cudaGetSymbolAddress((void**)&spk,  g_spk);
    cudaGetSymbolAddress((void**)&idx,  g_idx);

    // input prep (x padded to 96 ci)
    xprep_k<<<((long)B_SZ*T_LEN*96 + 255)/256, 256>>>(x, xh, xl);
    spknorm_k<<<128, 128>>>(spk_emb, spk);
    yeb_k<<<dim3(T_LEN/8, B_SZ), 256>>>(y, spk, yeh);

    // ===== encoder: bf16 3-product (MODE 0) =====
    wprep_k<<<(5*512*96+255)/256, 256>>>(enc_w1, wh, wl, 80, 512, 96, 512, 5, 0, 0);
    GEMM5(96, 0, 5, 0, xh, xl, 96, (const uint16_t*)nullptr, (const uint16_t*)nullptr, enc_b1, 512, 512, raw);
    ln_k<512,0,0><<<dim3(128, B_SZ), 256>>>(raw, enc_g1, enc_bt1, hAh, hAl);
    wprep_k<<<(5*512*512+255)/256, 256>>>(enc_w2, wh, wl, 512, 512, 512, 512, 5, 0, 0);
    GEMM5(512, 0, 5, 0, hAh, hAl, 512, (const uint16_t*)nullptr, (const uint16_t*)nullptr, enc_b2, 512, 512, raw);
    ln_k<512,0,0><<<dim3(128, B_SZ), 256>>>(raw, enc_g2, enc_bt2, hBh, hBl);
    wprep_k<<<(5*512*512+255)/256, 256>>>(enc_w3, wh, wl, 512, 512, 512, 512, 5, 0, 0);
    GEMM5(512, 0, 5, 0, hBh, hBl, 512, (const uint16_t*)nullptr, (const uint16_t*)nullptr, enc_b3, 512, 512, raw);
    ln_k<512,0,0><<<dim3(128, B_SZ), 256>>>(raw, enc_g3, enc_bt3, hAh, hAl);

    // ===== mlp 1x1 (bf16 3-product GEMM, K=1): 512 -> 64 (pad 128) =====
    wprep_k<<<(512*128+255)/256, 256>>>(mlp_w, wh, wl, 512, 64, 512, 128, 1, 0, 0);
    GEMM5(512, 0, 1, 0, hAh, hAl, 512, (const uint16_t*)nullptr, (const uint16_t*)nullptr, mlp_b, 64, 128, raw);
    zsplit_k<<<dim3(128, B_SZ), 256>>>(raw, xh, xl);   // z -> [b][t][64] bf16 hi/lo (xh/xl reused)

    // ===== VQ: scores = ||c||^2 - 2 z.c via GEMM (EPI 2), then argmin =====
    cbnorm_k<<<4, 128>>>(codebook, cbn);
    wprep_k<<<(64*512+255)/256, 256>>>(codebook, wh, wl, 64, 512, 64, 512, 1, 0, 0);
    GEMM5(64, 0, 1, 2, xh, xl, 64, (const uint16_t*)nullptr, (const uint16_t*)nullptr, cbn, 512, 512, raw);
    argmin_k<<<dim3(T_LEN/256, B_SZ), 256>>>(raw, idx);
    zvqb_k<<<dim3(T_LEN/8, B_SZ), 256>>>(idx, codebook, zvh);

    // ===== decoder: fp16 1-product (MODE 2) =====
    wprep_k<<<(5*1024*192+255)/256, 256>>>(dec_w1, wh, wl, 192, 1024, 192, 1024, 5, 1, 1);
    GEMM5(192, 2, 5, 0, zvh, (const uint16_t*)nullptr, 64, yeh, (const uint16_t*)nullptr, dec_b1, 1024, 1024, raw);
    ln_k<1024,1,1><<<dim3(128, B_SZ), 256>>>(raw, dec_g1, dec_bt1, hAh, nullptr);
    wprep_k<<<(5*1024*640+255)/256, 256>>>(dec_w2, wh, wl, 640, 1024, 640, 1024, 5, 1, 1);
    GEMM5(640, 2, 5, 0, hAh, (const uint16_t*)nullptr, 512, yeh, (const uint16_t*)nullptr, dec_b2, 1024, 1024, raw);
    ln_k<1024,1,1><<<dim3(128, B_SZ), 256>>>(raw, dec_g2, dec_bt2, hBh, nullptr);
    wprep_k<<<(5*128*640+255)/256, 256>>>(dec_w3, wh, wl, 640, 80, 640, 128, 5, 1, 1);
    GEMM5(640, 2, 5, 1, hBh, (const uint16_t*)nullptr, 512, yeh, (const uint16_t*)nullptr, dec_b3, 80, 128, outp);
}

// round 15
// speedup vs baseline: 1.1605x; 1.0276x over previous
#include <cuda_runtime.h>
#include <cuda_fp16.h>
#include <cuda_bf16.h>
#include <math.h>
#include <stdint.h>

#define T_LEN 4096
#define B_SZ  16

// ---------------- scratch ----------------
__device__ float    g_raw  [16ll*1024*4096];
__device__ uint16_t g_hAh[16ll*4096*512], g_hAl[16ll*4096*512];
__device__ uint16_t g_hBh[16ll*4096*512], g_hBl[16ll*4096*512];
__device__ uint16_t g_xh [16ll*4096*128], g_xl [16ll*4096*128];
__device__ uint16_t g_yeh[16ll*4096*128];
__device__ uint16_t g_zvh[16ll*4096*64];
__device__ uint16_t g_wh [5ll*1024*640],  g_wl [5ll*1024*640];
__device__ float    g_vs [4ll*16*4096];
__device__ int      g_vi [4ll*16*4096];
__device__ float    g_cbn[512];
__device__ float    g_spk[128*128];
__device__ int      g_idx[16*4096];

// ---------------- conversion helpers ----------------
__device__ __forceinline__ uint16_t f2bf(float v) {
    __nv_bfloat16 h = __float2bfloat16(v); return *(uint16_t*)&h;
}
__device__ __forceinline__ float bf2f(uint16_t u) {
    __nv_bfloat16 h = *(__nv_bfloat16*)&u; return __bfloat162float(h);
}
__device__ __forceinline__ uint16_t f2hf(float v) {
    __half h = __float2half(v); return *(uint16_t*)&h;
}

// ---------------- PTX helpers ----------------
__device__ __forceinline__ uint32_t s32(const void* p) {
    uint32_t a;
    asm("{ .reg .u64 t; cvta.to.shared.u64 t, %1; cvt.u32.u64 %0, t; }" : "=r"(a) : "l"(p));
    return a;
}
__device__ __forceinline__ void cpa16(uint32_t d, const void* s, bool v) {
    int sz = v ? 16 : 0;
    asm volatile("cp.async.cg.shared.global [%0], [%1], 16, %2;" :: "r"(d), "l"(s), "r"(sz) : "memory");
}
#define CP_COMMIT() asm volatile("cp.async.commit_group;" ::: "memory")
__device__ __forceinline__ void ldsm4(uint32_t* r, uint32_t a) {
    asm volatile("ldmatrix.sync.aligned.m8n8.x4.shared.b16 {%0,%1,%2,%3}, [%4];"
                 : "=r"(r[0]),"=r"(r[1]),"=r"(r[2]),"=r"(r[3]) : "r"(a));
}
__device__ __forceinline__ void mma_bf16(float* d, const uint32_t* a, const uint32_t* b) {
    asm volatile("mma.sync.aligned.m16n8k16.row.col.f32.bf16.bf16.f32 "
                 "{%0,%1,%2,%3}, {%4,%5,%6,%7}, {%8,%9}, {%0,%1,%2,%3};"
                 : "+f"(d[0]), "+f"(d[1]), "+f"(d[2]), "+f"(d[3])
                 : "r"(a[0]), "r"(a[1]), "r"(a[2]), "r"(a[3]), "r"(b[0]), "r"(b[1]));
}
__device__ __forceinline__ void mma_f16(float* d, const uint32_t* a, const uint32_t* b) {
    asm volatile("mma.sync.aligned.m16n8k16.row.col.f32.f16.f16.f32 "
                 "{%0,%1,%2,%3}, {%4,%5,%6,%7}, {%8,%9}, {%0,%1,%2,%3};"
                 : "+f"(d[0]), "+f"(d[1]), "+f"(d[2]), "+f"(d[3])
                 : "r"(a[0]), "r"(a[1]), "r"(a[2]), "r"(a[3]), "r"(b[0]), "r"(b[1]));
}

// ---------------- mma.sync implicit conv GEMM ----------------
// Block tile 128co x 128t, 8 warps, warp tile 64co x 32t.
// MODE 0: bf16, A hi/lo + B hi/lo, 3 products; MODE 2: fp16 single, 1 product.
// EPI 0: raw fp32 [b][co][t] (masked co<COUT)
// EPI 1: direct out fp32 [b][t][COUT] (dec3)
// EPI 3: VQ partial argmin over this CTA's 128 codes -> vs/vi [mo][b][t]
// EPI 4: raw fp16 [b][co][t] (decoder)
template<int CINP, int MODE, int KS, int EPI>
__global__ void __launch_bounds__(256,2) gemm5_k(
    const uint16_t* __restrict__ in1h, const uint16_t* __restrict__ in1l, int C1,
    const uint16_t* __restrict__ in2h, const uint16_t* __restrict__ in2l,
    const uint16_t* __restrict__ wh,   const uint16_t* __restrict__ wl,
    const float* __restrict__ bias, int COUT, int COUTP,
    float* __restrict__ raw, int* __restrict__ oidx)
{
    constexpr int NCH  = CINP / 32;
    constexpr int ITER = NCH * KS;
    constexpr int PAD  = (KS - 1) / 2;
    constexpr int IROWS = 128 + KS - 1;
    constexpr uint32_t B_BUF = (MODE == 0) ? 21120u : 10560u;
    constexpr uint32_t A_BUF = (MODE == 0) ? 20480u : 10240u;
    extern __shared__ char smc[];
    const uint32_t sb = s32(smc);
    const uint32_t B_OFF0 = 0u, B_OFF1 = B_BUF;
    const uint32_t A_OFF0 = 2u * B_BUF, A_OFF1 = 2u * B_BUF + A_BUF;

    const int tid = threadIdx.x, lane = tid & 31, wid = tid >> 5;
    const int mw = wid & 1, nw = wid >> 1;
    const int t0 = blockIdx.x * 128, b = blockIdx.y, mo = blockIdx.z;

    float acc[4][4][4];
    #pragma unroll
    for (int i = 0; i < 4; i++)
        #pragma unroll
        for (int j = 0; j < 4; j++)
            #pragma unroll
            for (int q = 0; q < 4; q++) acc[i][j][q] = 0.f;

    const uint32_t aRow = (uint32_t)(((lane >> 3) & 1) * 8 + (lane & 7));
    const uint32_t aCol = (uint32_t)((lane >> 4) * 16);
    const uint32_t bRow2 = (uint32_t)(((lane >> 4) & 1) * 8 + (lane & 7));
    const uint32_t bCol2 = (uint32_t)(((lane >> 3) & 1) * 16);

    auto issueB = [&](int ch, uint32_t boff) {
        int ci0 = ch * 32;
        const uint16_t *srch, *srcl; int Cs, off;
        if (ci0 < C1) { srch = in1h; srcl = in1l; Cs = C1;        off = ci0; }
        else          { srch = in2h; srcl = in2l; Cs = CINP - C1; off = ci0 - C1; }
        constexpr int HALF_E = IROWS * 4;
        constexpr int BE = (MODE == 0) ? 2 * HALF_E : HALF_E;
        for (int e = tid; e < BE; e += 256) {
            int half_ = (e >= HALF_E); int ee = half_ ? e - HALF_E : e;
            int row = ee >> 2, v = ee & 3;
            int t = t0 - PAD + row;
            bool ok = (t >= 0) & (t < T_LEN);
            int tc = ok ? t : 0;
            uint32_t d = sb + boff + (uint32_t)half_ * 10560u + (uint32_t)row * 80u + (uint32_t)v * 16u;
            const uint16_t* s = (half_ ? srcl : srch) + ((size_t)b * T_LEN + tc) * Cs + off + v * 8;
            cpa16(d, s, ok);
        }
    };
    auto issueA = [&](int it, uint32_t aoff) {
        int ch = it / KS, k = it % KS, ci0 = ch * 32;
        constexpr int AE = (MODE == 0) ? 1024 : 512;
        for (int e = tid; e < AE; e += 256) {
            int half_ = (e >= 512); int ee = e & 511;
            int row = ee >> 2, v = ee & 3;
            uint32_t d = sb + aoff + (uint32_t)half_ * 10240u + (uint32_t)row * 80u + (uint32_t)v * 16u;
            const uint16_t* s = (half_ ? wl : wh) + ((size_t)k * COUTP + mo * 128 + row) * CINP + ci0 + v * 8;
            cpa16(d, s, true);
        }
    };

    issueB(0, B_OFF0);
    issueA(0, A_OFF0);
    CP_COMMIT();

    for (int it = 0; it < ITER; it++) {
        int ch = it / KS, k = it % KS;
        uint32_t aoff = (it & 1) ? A_OFF1 : A_OFF0;
        uint32_t boff = (ch & 1) ? B_OFF1 : B_OFF0;
        asm volatile("cp.async.wait_group 0;" ::: "memory");
        __syncthreads();
        if (it + 1 < ITER) {
            int ch1 = (it + 1) / KS;
            if (ch1 != ch) issueB(ch1, (ch1 & 1) ? B_OFF1 : B_OFF0);
            issueA(it + 1, ((it + 1) & 1) ? A_OFF1 : A_OFF0);
            CP_COMMIT();
        }

        uint32_t aH = sb + aoff + (uint32_t)(mw * 64) * 80u;
        uint32_t bB = sb + boff + (uint32_t)(nw * 32 + k) * 80u;
        #pragma unroll
        for (int ks = 0; ks < 2; ks++) {
            uint32_t ah[4][4], bqh[2][4];
            uint32_t kOff = (uint32_t)ks * 32u;
            #pragma unroll
            for (int mt = 0; mt < 4; mt++) ldsm4(ah[mt], aH + (uint32_t)(mt * 16) * 80u + aRow * 80u + kOff + aCol);
            #pragma unroll
            for (int np = 0; np < 2; np++) ldsm4(bqh[np], bB + ((uint32_t)(np * 16) + bRow2) * 80u + kOff + bCol2);
            #pragma unroll
            for (int mt = 0; mt < 4; mt++)
                #pragma unroll
                for (int nt = 0; nt < 4; nt++) {
                    const uint32_t* bp = &bqh[nt >> 1][2 * (nt & 1)];
                    if constexpr (MODE == 0) mma_bf16(acc[mt][nt], ah[mt], bp);
                    else                     mma_f16 (acc[mt][nt], ah[mt], bp);
                }
            if constexpr (MODE == 0) {
                uint32_t bql[2][4], al[4][4];
                uint32_t bL = bB + 10560u;
                uint32_t aL = aH + 10240u;
                #pragma unroll
                for (int np = 0; np < 2; np++) ldsm4(bql[np], bL + ((uint32_t)(np * 16) + bRow2) * 80u + kOff + bCol2);
                #pragma unroll
                for (int mt = 0; mt < 4; mt++)
                    #pragma unroll
                    for (int nt = 0; nt < 4; nt++) mma_bf16(acc[mt][nt], ah[mt], &bql[nt >> 1][2 * (nt & 1)]);
                #pragma unroll
                for (int mt = 0; mt < 4; mt++) ldsm4(al[mt], aL + (uint32_t)(mt * 16) * 80u + aRow * 80u + kOff + aCol);
                #pragma unroll
                for (int mt = 0; mt < 4; mt++)
                    #pragma unroll
                    for (int nt = 0; nt < 4; nt++) mma_bf16(acc[mt][nt], al[mt], &bqh[nt >> 1][2 * (nt & 1)]);
            }
        }
    }

    // epilogue
    const int r = lane >> 2, c = (lane & 3) * 2;
    if constexpr (EPI == 3) {
        // VQ partial argmin over this CTA's 128 codes
        float bs[4][2]; int bi[4][2];
        #pragma unroll
        for (int nt = 0; nt < 4; nt++)
            #pragma unroll
            for (int sub = 0; sub < 2; sub++) { bs[nt][sub] = 3.4e38f; bi[nt][sub] = 0; }
        #pragma unroll
        for (int mt = 0; mt < 4; mt++) {
            int co0 = mw * 64 + mt * 16 + r;      // local 0..127
            int co1 = co0 + 8;
            float bv0 = bias[mo * 128 + co0];
            float bv1 = bias[mo * 128 + co1];
            #pragma unroll
            for (int nt = 0; nt < 4; nt++)
                #pragma unroll
                for (int sub = 0; sub < 2; sub++) {
                    float v0 = bv0 - 2.f * acc[mt][nt][sub];
                    float v1 = bv1 - 2.f * acc[mt][nt][2 + sub];
                    if (v0 < bs[nt][sub] || (v0 == bs[nt][sub] && co0 < bi[nt][sub])) { bs[nt][sub] = v0; bi[nt][sub] = co0; }
                    if (v1 < bs[nt][sub] || (v1 == bs[nt][sub] && co1 < bi[nt][sub])) { bs[nt][sub] = v1; bi[nt][sub] = co1; }
                }
        }
        #pragma unroll
        for (int off = 4; off <= 16; off <<= 1)
            #pragma unroll
            for (int nt = 0; nt < 4; nt++)
                #pragma unroll
                for (int sub = 0; sub < 2; sub++) {
                    float vs_ = __shfl_xor_sync(0xffffffffu, bs[nt][sub], off);
                    int   vi_ = __shfl_xor_sync(0xffffffffu, bi[nt][sub], off);
                    if (vs_ < bs[nt][sub] || (vs_ == bs[nt][sub] && vi_ < bi[nt][sub])) { bs[nt][sub] = vs_; bi[nt][sub] = vi_; }
                }
        __syncthreads();               // mainloop smem reads done before reuse
        float* sS = (float*)smc;       // [2][128]
        int*   sI = (int*)(smc + 2*128*4);
        if ((lane & 31) < 4) {
            int sc = lane & 3;
            #pragma unroll
            for (int nt = 0; nt < 4; nt++)
                #pragma unroll
                for (int sub = 0; sub < 2; sub++) {
                    int tl = nw * 32 + nt * 8 + sc * 2 + sub;
                    sS[mw * 128 + tl] = bs[nt][sub];
                    sI[mw * 128 + tl] = bi[nt][sub];
                }
        }
        __syncthreads();
        if (tid < 128) {
            float s0 = sS[tid], s1 = sS[128 + tid];
            int   i0 = sI[tid], i1 = sI[128 + tid];
            if (s1 < s0 || (s1 == s0 && i1 < i0)) { s0 = s1; i0 = i1; }
            size_t go = ((size_t)(mo * B_SZ + b)) * T_LEN + t0 + tid;
            raw[go] = s0;
            oidx[go] = i0;
        }
        return;
    }
    {
        #pragma unroll
        for (int mt = 0; mt < 4; mt++) {
            int co0 = mo * 128 + mw * 64 + mt * 16 + r;
            int co1 = co0 + 8;
            float bv0 = (co0 < COUT) ? bias[co0] : 0.f;
            float bv1 = (co1 < COUT) ? bias[co1] : 0.f;
            #pragma unroll
            for (int nt = 0; nt < 4; nt++) {
                int t = t0 + nw * 32 + nt * 8 + c;
                if constexpr (EPI == 1) {
                    if (co0 < COUT) {
                        raw[((size_t)b * T_LEN + t)     * COUT + co0] = acc[mt][nt][0] + bv0;
                        raw[((size_t)b * T_LEN + t + 1) * COUT + co0] = acc[mt][nt][1] + bv0;
                    }
                    if (co1 < COUT) {
                        raw[((size_t)b * T_LEN + t)     * COUT + co1] = acc[mt][nt][2] + bv1;
                        raw[((size_t)b * T_LEN + t + 1) * COUT + co1] = acc[mt][nt][3] + bv1;
                    }
                } else if constexpr (EPI == 4) {
                    __half* hr = (__half*)raw;
                    __half2 v0 = __floats2half2_rn(acc[mt][nt][0] + bv0, acc[mt][nt][1] + bv0);
                    __half2 v1 = __floats2half2_rn(acc[mt][nt][2] + bv1, acc[mt][nt][3] + bv1);
                    *(__half2*)(hr + ((size_t)b * COUTP + co0) * T_LEN + t) = v0;
                    *(__half2*)(hr + ((size_t)b * COUTP + co1) * T_LEN + t) = v1;
                } else {
                    if (co0 < COUT) {
                        float2 v0; v0.x = acc[mt][nt][0] + bv0; v0.y = acc[mt][nt][1] + bv0;
                        *(float2*)(raw + ((size_t)b * COUTP + co0) * T_LEN + t) = v0;
                    }
                    if (co1 < COUT) {
                        float2 v1; v1.x = acc[mt][nt][2] + bv1; v1.y = acc[mt][nt][3] + bv1;
                        *(float2*)(raw + ((size_t)b * COUTP + co1) * T_LEN + t) = v1;
                    }
                }
            }
        }
    }
}

// ---------------- LN + act + transpose + 16-bit output ----------------
// OUT: 0 = bf16 hi/lo pair, 1 = fp16 single.  HIN: 1 = fp16 raw input.
template<int CRAW,int GLU,int OUT,int HIN>
__global__ void __launch_bounds__(256) ln_k(const void* __restrict__ rawv,
    const float* __restrict__ ga, const float* __restrict__ be,
    uint16_t* __restrict__ oh, uint16_t* __restrict__ ol)
{
    constexpr int COUT = GLU ? CRAW/2 : CRAW;
    __shared__ float sS[8][33], sQ[8][33], sM[32], sR[32];
    __shared__ uint16_t sTh[32*66], sTl[32*66];
    int b = blockIdx.y, t0 = blockIdx.x*32;
    int wg = threadIdx.x>>5, tt = threadIdx.x&31;
    const float* rf = (const float*)rawv + (size_t)b*CRAW*T_LEN + t0 + tt;
    const __half* rh = (const __half*)rawv + (size_t)b*CRAW*T_LEN + t0 + tt;
    auto rd = [&](int cc) -> float {
        if (HIN) return __half2float(rh[(size_t)cc*T_LEN]);
        return rf[(size_t)cc*T_LEN];
    };
    float s=0.f, q=0.f;
    for (int cc=wg; cc<CRAW; cc+=8){ float v=rd(cc); s+=v; q+=v*v; }
    sS[wg][tt]=s; sQ[wg][tt]=q; __syncthreads();
    if (threadIdx.x<32){
        float S=0.f,Q=0.f;
        for(int g2=0;g2<8;g2++){S+=sS[g2][threadIdx.x];Q+=sQ[g2][threadIdx.x];}
        float m=S*(1.f/CRAW); float v=Q*(1.f/CRAW)-m*m;
        sM[threadIdx.x]=m; sR[threadIdx.x]=rsqrtf(v+1e-5f);
    }
    __syncthreads();
    float m=sM[tt], r=sR[tt];
    for (int c0=0;c0<COUT;c0+=64){
        #pragma unroll
        for (int i=0;i<8;i++){
            int cc=c0+wg+8*i;
            float a=(rd(cc)-m)*r*ga[cc]+be[cc];
            if (GLU){
                float gt=(rd(cc+COUT)-m)*r*ga[cc+COUT]+be[cc+COUT];
                a=a*(1.f/(1.f+expf(-gt)));
            } else a = a>0.f? a : 0.2f*a;
            if constexpr (OUT == 0) {
                uint16_t h = f2bf(a);
                sTh[tt*66 + wg+8*i] = h;
                sTl[tt*66 + wg+8*i] = f2bf(a - bf2f(h));
            } else {
                sTh[tt*66 + wg+8*i] = f2hf(a);
            }
        }
        __syncthreads();
        {
            int row=threadIdx.x>>3, v=threadIdx.x&7;
            const uint32_t* ph=(const uint32_t*)sTh + row*33 + v*4;
            size_t go=((size_t)b*T_LEN + t0+row)*COUT + c0 + v*8;
            *(uint4*)(oh+go)=make_uint4(ph[0],ph[1],ph[2],ph[3]);
            if constexpr (OUT == 0) {
                const uint32_t* pl=(const uint32_t*)sTl + row*33 + v*4;
                *(uint4*)(ol+go)=make_uint4(pl[0],pl[1],pl[2],pl[3]);
            }
        }
        __syncthreads();
    }
}

// ---------------- z split: raw [b][128][t] (64 valid) -> bf16 hi/lo [b][t][64] ----------------
__global__ void __launch_bounds__(256) zsplit_k(const float* __restrict__ raw,
    uint16_t* __restrict__ oh, uint16_t* __restrict__ ol)
{
    __shared__ uint16_t sTh[32*66], sTl[32*66];
    int b = blockIdx.y, t0 = blockIdx.x*32;
    int wg = threadIdx.x>>5, tt = threadIdx.x&31;
    const float* rb = raw + (size_t)b*128*T_LEN + t0 + tt;
    #pragma unroll
    for (int i=0;i<8;i++){
        int cc=wg+8*i;
        float a=rb[(size_t)cc*T_LEN];
        uint16_t h = f2bf(a);
        sTh[tt*66 + cc] = h;
        sTl[tt*66 + cc] = f2bf(a - bf2f(h));
    }
    __syncthreads();
    {
        int row=threadIdx.x>>3, v=threadIdx.x&7;
        const uint32_t* ph=(const uint32_t*)sTh + row*33 + v*4;
        const uint32_t* pl=(const uint32_t*)sTl + row*33 + v*4;
        size_t go=((size_t)b*T_LEN + t0+row)*64 + v*8;
        *(uint4*)(oh+go)=make_uint4(ph[0],ph[1],ph[2],ph[3]);
        *(uint4*)(ol+go)=make_uint4(pl[0],pl[1],pl[2],pl[3]);
    }
}

// ---------------- final VQ reduce over 4 mo partials ----------------
__global__ void __launch_bounds__(256) argmin2_k(const float* __restrict__ vs,
    const int* __restrict__ vi, int* __restrict__ idx)
{
    int b = blockIdx.y, t = blockIdx.x*256 + threadIdx.x;
    float best = 3.4e38f; int bi = 0;
    #pragma unroll
    for (int mo = 0; mo < 4; mo++) {
        size_t go = ((size_t)(mo * B_SZ + b)) * T_LEN + t;
        float v = vs[go];
        int   i = vi[go] + mo * 128;
        if (v < best || (v == best && i < bi)) { best = v; bi = i; }
    }
    idx[(size_t)b*T_LEN + t] = bi;
}

// ---------------- small helpers ----------------
__global__ void spknorm_k(const float* __restrict__ spk, float* __restrict__ o) {
    __shared__ float red[128];
    int r = blockIdx.x, t = threadIdx.x;
    float v = spk[r*128 + t];
    red[t] = v*v; __syncthreads();
    for (int s = 64; s > 0; s >>= 1) { if (t < s) red[t] += red[t+s]; __syncthreads(); }
    o[r*128 + t] = v * rsqrtf(red[0]);
}
__global__ void cbnorm_k(const float* __restrict__ cb, float* __restrict__ n) {
    int c = blockIdx.x*128 + threadIdx.x;
    if (c < 512) { float s=0.f; for (int d=0; d<64; d++){ float v=cb[c*64+d]; s+=v*v; } n[c]=s; }
}
__global__ void xprep_k(const float* __restrict__ x, uint16_t* __restrict__ oh, uint16_t* __restrict__ ol) {
    long e = (long)blockIdx.x*256 + threadIdx.x;
    if (e >= (long)B_SZ*T_LEN*96) return;
    int c = (int)(e % 96); long bt = e / 96;
    float v = (c < 80) ? x[bt*80 + c] : 0.f;
    uint16_t h = f2bf(v);
    oh[e] = h; ol[e] = f2bf(v - bf2f(h));
}
__global__ void yeb_k(const int* __restrict__ y, const float* __restrict__ spk,
                      uint16_t* __restrict__ oh) {
    int b = blockIdx.y, t = blockIdx.x*8 + (threadIdx.x>>5), lid = threadIdx.x & 31;
    int yi = y[(size_t)b*T_LEN + t];
    size_t base = ((size_t)b*T_LEN + t) * 128;
    for (int c = lid; c < 128; c += 32)
        oh[base+c] = f2hf(spk[yi*128 + c]);
}
__global__ void zvqb_k(const int* __restrict__ idx, const float* __restrict__ cb,
                       uint16_t* __restrict__ oh) {
    int b = blockIdx.y, t = blockIdx.x*8 + (threadIdx.x>>5), lid = threadIdx.x & 31;
    int ii = idx[(size_t)b*T_LEN + t];
    size_t base = ((size_t)b*T_LEN + t) * 64;
    for (int c = lid; c < 64; c += 32)
        oh[base+c] = f2hf(cb[ii*64 + c]);
}
__global__ void wprep_k(const float* __restrict__ w, uint16_t* __restrict__ wh, uint16_t* __restrict__ wl,
                        int CIN, int COUT, int CINP, int COUTP, int K, int dec, int mode) {
    long e = (long)blockIdx.x*256 + threadIdx.x;
    if (e >= (long)K*COUTP*CINP) return;
    int ci = (int)(e % CINP); long r0 = e / CINP; int co = (int)(r0 % COUTP); int k = (int)(r0 / COUTP);
    float v = 0.f;
    if (ci < CIN && co < COUT)
        v = dec ? w[((size_t)ci*COUT + co)*K + (K-1-k)] : w[((size_t)co*CIN + ci)*K + k];
    if (mode == 0) {
        uint16_t h = f2bf(v);
        wh[e] = h; wl[e] = f2bf(v - bf2f(h));
    } else {
        wh[e] = f2hf(v);
    }
}

// ---------------- launch ----------------
#define GEMM5(CINP_, MODE_, KS_, EPI_, i1h,i1l,C1_, i2h,i2l, biasp, COUT_, COUTP_, outp_, oidx_) do { \
    constexpr int SMB_ = ((MODE_) == 0) ? (2*21120 + 2*20480) : (2*10560 + 2*10240); \
    auto kf = &gemm5_k<CINP_, MODE_, KS_, EPI_>; \
    cudaFuncSetAttribute(kf, cudaFuncAttributeMaxDynamicSharedMemorySize, SMB_); \
    kf<<<dim3(32, B_SZ, (COUTP_)/128), 256, SMB_>>>(i1h,i1l,C1_, i2h,i2l, wh,wl, biasp, COUT_, COUTP_, outp_, oidx_); \
} while (0)

extern "C" void kernel_launch(void* const* d_in, const int* in_sizes, int n_in,
                              void* d_out, int out_size) {
    (void)in_sizes; (void)n_in; (void)out_size;
    const float* x       = (const float*)d_in[0];
    const int*   y       = (const int*)  d_in[1];
    const float* enc_w1  = (const float*)d_in[2];
    const float* enc_b1  = (const float*)d_in[3];
    const float* enc_g1  = (const float*)d_in[4];
    const float* enc_bt1 = (const float*)d_in[5];
    const float* enc_w2  = (const float*)d_in[6];
    const float* enc_b2  = (const float*)d_in[7];
    const float* enc_g2  = (const float*)d_in[8];
    const float* enc_bt2 = (const float*)d_in[9];
    const float* enc_w3  = (const float*)d_in[10];
    const float* enc_b3  = (const float*)d_in[11];
    const float* enc_g3  = (const float*)d_in[12];
    const float* enc_bt3 = (const float*)d_in[13];
    const float* mlp_w   = (const float*)d_in[14];
    const float* mlp_b   = (const float*)d_in[15];
    const float* codebook= (const float*)d_in[16];
    const float* spk_emb = (const float*)d_in[17];
    const float* dec_w1  = (const float*)d_in[18];
    const float* dec_b1  = (const float*)d_in[19];
    const float* dec_g1  = (const float*)d_in[20];
    const float* dec_bt1 = (const float*)d_in[21];
    const float* dec_w2  = (const float*)d_in[22];
    const float* dec_b2  = (const float*)d_in[23];
    const float* dec_g2  = (const float*)d_in[24];
    const float* dec_bt2 = (const float*)d_in[25];
    const float* dec_w3  = (const float*)d_in[26];
    const float* dec_b3  = (const float*)d_in[27];
    float* outp = (float*)d_out;

    float *raw,*vs,*cbn,*spk; int *vi,*idx;
    uint16_t *hAh,*hAl,*hBh,*hBl,*xh,*xl,*yeh,*zvh,*wh,*wl;
    cudaGetSymbolAddress((void**)&raw,  g_raw);
    cudaGetSymbolAddress((void**)&hAh,  g_hAh);  cudaGetSymbolAddress((void**)&hAl, g_hAl);
    cudaGetSymbolAddress((void**)&hBh,  g_hBh);  cudaGetSymbolAddress((void**)&hBl, g_hBl);
    cudaGetSymbolAddress((void**)&xh,   g_xh);   cudaGetSymbolAddress((void**)&xl,  g_xl);
    cudaGetSymbolAddress((void**)&yeh,  g_yeh);
    cudaGetSymbolAddress((void**)&zvh,  g_zvh);
    cudaGetSymbolAddress((void**)&wh,   g_wh);   cudaGetSymbolAddress((void**)&wl,  g_wl);
    cudaGetSymbolAddress((void**)&vs,   g_vs);   cudaGetSymbolAddress((void**)&vi,  g_vi);
    cudaGetSymbolAddress((void**)&cbn,  g_cbn);
    cudaGetSymbolAddress((void**)&spk,  g_spk);
    cudaGetSymbolAddress((void**)&idx,  g_idx);

    // input prep (x padded to 96 ci)
    xprep_k<<<((long)B_SZ*T_LEN*96 + 255)/256, 256>>>(x, xh, xl);
    spknorm_k<<<128, 128>>>(spk_emb, spk);
    yeb_k<<<dim3(T_LEN/8, B_SZ), 256>>>(y, spk, yeh);

    // ===== encoder: bf16 3-product (MODE 0), raw fp32 =====
    wprep_k<<<(5*512*96+255)/256, 256>>>(enc_w1, wh, wl, 80, 512, 96, 512, 5, 0, 0);
    GEMM5(96, 0, 5, 0, xh, xl, 96, (const uint16_t*)nullptr, (const uint16_t*)nullptr, enc_b1, 512, 512, raw, (int*)nullptr);
    ln_k<512,0,0,0><<<dim3(128, B_SZ), 256>>>(raw, enc_g1, enc_bt1, hAh, hAl);
    wprep_k<<<(5*512*512+255)/256, 256>>>(enc_w2, wh, wl, 512, 512, 512, 512, 5, 0, 0);
    GEMM5(512, 0, 5, 0, hAh, hAl, 512, (const uint16_t*)nullptr, (const uint16_t*)nullptr, enc_b2, 512, 512, raw, (int*)nullptr);
    ln_k<512,0,0,0><<<dim3(128, B_SZ), 256>>>(raw, enc_g2, enc_bt2, hBh, hBl);
    wprep_k<<<(5*512*512+255)/256, 256>>>(enc_w3, wh, wl, 512, 512, 512, 512, 5, 0, 0);
    GEMM5(512, 0, 5, 0, hBh, hBl, 512, (const uint16_t*)nullptr, (const uint16_t*)nullptr, enc_b3, 512, 512, raw, (int*)nullptr);
    ln_k<512,0,0,0><<<dim3(128, B_SZ), 256>>>(raw, enc_g3, enc_bt3, hAh, hAl);

    // ===== mlp 1x1 (bf16 3-product, K=1): 512 -> 64 (pad 128), raw fp32 masked =====
    wprep_k<<<(512*128+255)/256, 256>>>(mlp_w, wh, wl, 512, 64, 512, 128, 1, 0, 0);
    GEMM5(512, 0, 1, 0, hAh, hAl, 512, (const uint16_t*)nullptr, (const uint16_t*)nullptr, mlp_b, 64, 128, raw, (int*)nullptr);
    zsplit_k<<<dim3(128, B_SZ), 256>>>(raw, xh, xl);

    // ===== VQ: fused partial argmin in GEMM epilogue, then 4-way reduce =====
    cbnorm_k<<<4, 128>>>(codebook, cbn);
    wprep_k<<<(64*512+255)/256, 256>>>(codebook, wh, wl, 64, 512, 64, 512, 1, 0, 0);
    GEMM5(64, 0, 1, 3, xh, xl, 64, (const uint16_t*)nullptr, (const uint16_t*)nullptr, cbn, 512, 512, vs, vi);
    argmin2_k<<<dim3(T_LEN/256, B_SZ), 256>>>(vs, vi, idx);
    zvqb_k<<<dim3(T_LEN/8, B_SZ), 256>>>(idx, codebook, zvh);

    // ===== decoder: fp16 1-product (MODE 2), raw fp16 =====
    wprep_k<<<(5*1024*192+255)/256, 256>>>(dec_w1, wh, wl, 192, 1024, 192, 1024, 5, 1, 1);
    GEMM5(192, 2, 5, 4, zvh, (const uint16_t*)nullptr, 64, yeh, (const uint16_t*)nullptr, dec_b1, 1024, 1024, raw, (int*)nullptr);
    ln_k<1024,1,1,1><<<dim3(128, B_SZ), 256>>>(raw, dec_g1, dec_bt1, hAh, nullptr);
    wprep_k<<<(5*1024*640+255)/256, 256>>>(dec_w2, wh, wl, 640, 1024, 640, 1024, 5, 1, 1);
    GEMM5(640, 2, 5, 4, hAh, (const uint16_t*)nullptr, 512, yeh, (const uint16_t*)nullptr, dec_b2, 1024, 1024, raw, (int*)nullptr);
    ln_k<1024,1,1,1><<<dim3(128, B_SZ), 256>>>(raw, dec_g2, dec_bt2, hBh, nullptr);
    wprep_k<<<(5*128*640+255)/256, 256>>>(dec_w3, wh, wl, 640, 80, 640, 128, 5, 1, 1);
    GEMM5(640, 2, 5, 1, hBh, (const uint16_t*)nullptr, 512, yeh, (const uint16_t*)nullptr, dec_b3, 80, 128, outp, (int*)nullptr);
}